// round 2
// baseline (speedup 1.0000x reference)
#include <cuda_runtime.h>

#define BSZ 128
#define NN 48
#define NP1 49
#define DM 32
#define DMODEL 128
#define NHEAD 4
#define HD 32
#define TOTALE (BSZ*NN*NHEAD*NP1)   /* 1204224 */

// ---------------- device scratch (allowed: __device__ globals) ----------------
__device__ float g_P[BSZ * NP1 * DMODEL];                 // xn @ W_embed[0:32] + b_embed
__device__ float g_Q[BSZ * NN * DMODEL];                  // x  @ W_embed[32:64]
__device__ float g_E[(size_t)BSZ * NN * NP1 * DMODEL];    // LayerNormed E, layout [b][j][i][d]

// ---------------- helpers ----------------
__device__ __forceinline__ float warp_sum(float v) {
    #pragma unroll
    for (int o = 16; o > 0; o >>= 1) v += __shfl_xor_sync(0xffffffffu, v, o);
    return v;
}
__device__ __forceinline__ float warp_max(float v) {
    #pragma unroll
    for (int o = 16; o > 0; o >>= 1) v = fmaxf(v, __shfl_xor_sync(0xffffffffu, v, o));
    return v;
}
__device__ __forceinline__ unsigned rotl32(unsigned v, int r) {
    return (v << r) | (v >> (32 - r));
}

// JAX partitionable-threefry gumbel noise (jax_threefry_partitionable=True,
// default since JAX 0.4.36):
//   per element i: (b1,b2) = threefry2x32(key=(0,42), (hi32(i)=0, lo32(i)=i))
//   bits = b1 ^ b2
//   u = bitcast((bits>>9)|0x3f800000) - 1        (uniform [0,1))
//   exp = -log1p(-u) ; gumbel = -log(exp)
__device__ float gumbel_noise(unsigned idx) {
    unsigned x0 = 0u, x1 = idx;
    const unsigned ks0 = 0u, ks1 = 42u, ks2 = 0x1BD11BDAu ^ 0u ^ 42u;
    x0 += ks0; x1 += ks1;
#define TFR(r) { x0 += x1; x1 = rotl32(x1, r); x1 ^= x0; }
    TFR(13) TFR(15) TFR(26) TFR(6)   x0 += ks1; x1 += ks2 + 1u;
    TFR(17) TFR(29) TFR(16) TFR(24)  x0 += ks2; x1 += ks0 + 2u;
    TFR(13) TFR(15) TFR(26) TFR(6)   x0 += ks0; x1 += ks1 + 3u;
    TFR(17) TFR(29) TFR(16) TFR(24)  x0 += ks1; x1 += ks2 + 4u;
    TFR(13) TFR(15) TFR(26) TFR(6)   x0 += ks2; x1 += ks0 + 5u;
#undef TFR
    unsigned bits = x0 ^ x1;
    float u = __uint_as_float((bits >> 9) | 0x3f800000u) - 1.0f; // uniform [0,1)
    float ex = -log1pf(-u);                                      // exponential sample
    return -logf(ex);                                            // gumbel
}

// ---------------- kernel 1: P[b,i,:] and Q[b,j,:] ----------------
// grid (BSZ*NP1), block 128 (thread = d)
__global__ void k1_pq(const float* __restrict__ x,
                      const float* __restrict__ attn_mask,
                      const float* __restrict__ W_embed,
                      const float* __restrict__ b_embed) {
    int b = blockIdx.x / NP1;
    int n = blockIdx.x % NP1;
    int d = threadIdx.x;
    if (n == NN) {  // ghost node: xn row is zero -> P = b_embed
        g_P[((size_t)b * NP1 + NN) * DMODEL + d] = b_embed[d];
        return;
    }
    __shared__ float am[NN];
    __shared__ float xm[DM];
    if (d < NN) am[d] = attn_mask[((size_t)b * NN + n) * NN + d];
    __syncthreads();
    float s = 0.f;
    #pragma unroll
    for (int c = 0; c < NN; c++) s += am[c];
    float ped = (s > 0.f) ? 1.f : 0.f;
    if (d < DM) xm[d] = x[((size_t)b * NN + n) * DM + d] * ped;
    __syncthreads();
    float p = b_embed[d];
    float q = 0.f;
    #pragma unroll
    for (int c = 0; c < DM; c++) {
        float xc = xm[c];
        p = fmaf(xc, W_embed[c * DMODEL + d], p);
        q = fmaf(xc, W_embed[(DM + c) * DMODEL + d], q);
    }
    g_P[((size_t)b * NP1 + n) * DMODEL + d] = p;
    g_Q[((size_t)b * NN + n) * DMODEL + d] = q;
}

// ---------------- kernel 2: E + LayerNorm, stored as [b][j][i][d] ----------------
// grid (BSZ*NN) = one (b,j) per block, 256 threads (8 warps; warp handles rows i=w,w+8,...)
__global__ void __launch_bounds__(256) k2_embed_ln(
    const float* __restrict__ A,
    const float* __restrict__ attn_mask,
    const float* __restrict__ W_embed,
    const float* __restrict__ ln_g,
    const float* __restrict__ ln_b) {
    int bj = blockIdx.x;
    int b = bj / NN, j = bj % NN;
    __shared__ float sWA[DM * DMODEL];   // W_embed rows 64..95
    __shared__ float sg[DMODEL], sb[DMODEL];
    int tid = threadIdx.x, lane = tid & 31, w = tid >> 5;
    for (int t = tid; t < DM * DMODEL; t += 256) sWA[t] = W_embed[(2 * DM) * DMODEL + t];
    if (tid < DMODEL) { sg[tid] = ln_g[tid]; sb[tid] = ln_b[tid]; }
    __syncthreads();

    const float* Pb = g_P + (size_t)b * NP1 * DMODEL;
    const float* Qb = g_Q + ((size_t)b * NN + j) * DMODEL;
    float qv[4];
    #pragma unroll
    for (int r = 0; r < 4; r++) qv[r] = Qb[lane + 32 * r];

    for (int i = w; i < NP1; i += 8) {
        float a = 0.f;
        if (i < NN) {
            float mk = attn_mask[((size_t)b * NN + j) * NN + i];  // attn_mask[b, target=j, neighbor=i]
            a = A[(((size_t)b * NN + i) * NN + j) * DM + lane] * mk;
        }
        float e[4];
        #pragma unroll
        for (int r = 0; r < 4; r++) e[r] = Pb[i * DMODEL + lane + 32 * r] + qv[r];
        #pragma unroll
        for (int c = 0; c < DM; c++) {
            float ac = __shfl_sync(0xffffffffu, a, c);
            #pragma unroll
            for (int r = 0; r < 4; r++) e[r] = fmaf(ac, sWA[c * DMODEL + lane + 32 * r], e[r]);
        }
        // LayerNorm over 128 (4 per lane)
        float ls = e[0] + e[1] + e[2] + e[3];
        float mu = warp_sum(ls) * (1.0f / DMODEL);
        float sq = 0.f;
        #pragma unroll
        for (int r = 0; r < 4; r++) { float dv = e[r] - mu; sq += dv * dv; }
        float var = warp_sum(sq) * (1.0f / DMODEL);
        float rs = rsqrtf(var + 1e-5f);
        float* dst = g_E + (((size_t)bj * NP1) + i) * DMODEL;
        #pragma unroll
        for (int r = 0; r < 4; r++) {
            int d = lane + 32 * r;
            dst[d] = (e[r] - mu) * rs * sg[d] + sb[d];
        }
    }
}

// ---------------- kernel 3: fused qkv + attention + MLP + em + gumbel ----------------
// smem layout (floats)
#define OFF_E   0          /* 49*128 = 6272 */
#define OFF_Q   6272       /* 6272 */
#define OFF_V   12544      /* 6272 */
#define OFF_KT  18816      /* 128*65 = 8320 (K transposed, padded) */
#define OFF_S   27136      /* 4*49*52 = 10192 attn */
#define OFF_WT  37328      /* 32*384 = 12288 W tile */
#define OFF_M   49616      /* 64 */
#define OFF_G   49680      /* 200 gate logits */
#define OFF_BQ  49880      /* 384 */
#define OFF_W1  50264      /* 1024 */
#define OFF_B1  51288      /* 32 */
#define OFF_W2  51320      /* 32 */
#define SMEM3_FLOATS 51352
#define SMEM3_BYTES (SMEM3_FLOATS * 4)

__global__ void __launch_bounds__(256, 1) k3_attn(
    const float* __restrict__ attn_mask,
    const float* __restrict__ W_qkv,
    const float* __restrict__ b_qkv,
    const float* __restrict__ W1,
    const float* __restrict__ b1,
    const float* __restrict__ W2,
    const float* __restrict__ b2,
    float* __restrict__ out) {
    extern __shared__ float sm[];
    int bj = blockIdx.x;
    int b = bj / NN, j = bj % NN;
    int tid = threadIdx.x, lane = tid & 31, w = tid >> 5;

    float* sE = sm + OFF_E;
    float* sQ = sm + OFF_Q;
    float* sV = sm + OFF_V;
    float* sKT = sm + OFF_KT;
    float* sS = sm + OFF_S;
    float* wt = sm + OFF_WT;
    float* sM = sm + OFF_M;
    float* sG = sm + OFF_G;
    float* sBq = sm + OFF_BQ;
    float* sW1 = sm + OFF_W1;
    float* sb1 = sm + OFF_B1;
    float* sW2 = sm + OFF_W2;

    // ---- init loads ----
    {
        const float4* src = (const float4*)(g_E + (size_t)bj * NP1 * DMODEL);
        float4* dst = (float4*)sE;
        for (int t = tid; t < NP1 * DMODEL / 4; t += 256) dst[t] = src[t];
    }
    if (tid < NP1) sM[tid] = (tid < NN) ? attn_mask[((size_t)b * NN + j) * NN + tid] : 1.0f;
    for (int t = tid; t < 384; t += 256) sBq[t] = b_qkv[t];
    for (int t = tid; t < 1024; t += 256) sW1[t] = W1[t];
    if (tid < 32) { sb1[tid] = b1[tid]; sW2[tid] = W2[tid]; }
    for (int t = tid; t < 128 * 65; t += 256) sKT[t] = 0.f;  // zero pad rows 49..64
    __syncthreads();

    // ---- qkv GEMM: rows assigned per warp (i = w, w+8, ...), lanes over cols ----
    float acc[7][12];
    #pragma unroll
    for (int rr = 0; rr < 7; rr++)
        #pragma unroll
        for (int k = 0; k < 12; k++) acc[rr][k] = 0.f;

    for (int d0 = 0; d0 < DMODEL; d0 += 32) {
        for (int t = tid; t < 32 * 384 / 4; t += 256)
            ((float4*)wt)[t] = ((const float4*)(W_qkv + (size_t)d0 * 384))[t];
        __syncthreads();
        #pragma unroll 4
        for (int dd = 0; dd < 32; dd++) {
            float wv[12];
            #pragma unroll
            for (int k = 0; k < 12; k++) wv[k] = wt[dd * 384 + lane + 32 * k];
            #pragma unroll
            for (int rr = 0; rr < 7; rr++) {
                int row = w + 8 * rr;
                if (row < NP1) {
                    float e = sE[row * DMODEL + d0 + dd];
                    #pragma unroll
                    for (int k = 0; k < 12; k++) acc[rr][k] = fmaf(e, wv[k], acc[rr][k]);
                }
            }
        }
        __syncthreads();
    }
    // scatter q / k^T / v with bias
    #pragma unroll
    for (int rr = 0; rr < 7; rr++) {
        int row = w + 8 * rr;
        if (row < NP1) {
            #pragma unroll
            for (int k = 0; k < 12; k++) {
                int col = lane + 32 * k;
                float v = acc[rr][k] + sBq[col];
                if (k < 4)       sQ[row * DMODEL + col] = v;
                else if (k < 8)  sKT[(col - 128) * 65 + row] = v;
                else             sV[row * DMODEL + (col - 256)] = v;
            }
        }
    }
    __syncthreads();

    // ---- scores + softmax: one warp per (h, i); lanes cover neighbor jj ----
    const float scale = 0.1767766952966369f;  // 32^-0.5
    for (int task = w; task < NHEAD * NP1; task += 8) {
        int h = task & 3;
        int i = task >> 2;
        float mi = sM[i];
        int j0 = lane, j1 = lane + 32;
        bool has1 = (j1 < NP1);
        float s0 = 0.f, s1 = 0.f;
        #pragma unroll
        for (int d = 0; d < HD; d++) {
            float qv = sQ[i * DMODEL + h * HD + d];
            s0 = fmaf(qv, sKT[(h * HD + d) * 65 + j0], s0);
            s1 = fmaf(qv, sKT[(h * HD + d) * 65 + j1], s1);
        }
        float pm0 = mi * sM[j0];
        s0 = (pm0 > 0.f) ? s0 * scale : -1e9f;
        float pm1 = has1 ? mi * sM[j1] : 0.f;
        s1 = (has1 && pm1 > 0.f) ? s1 * scale : -1e9f;
        float mx = warp_max(fmaxf(s0, has1 ? s1 : -INFINITY));
        float e0 = expf(s0 - mx);
        float e1 = has1 ? expf(s1 - mx) : 0.f;
        float inv = 1.0f / warp_sum(e0 + e1);
        float* srow = sS + (h * NP1 + i) * 52;
        srow[j0] = e0 * inv;
        if (has1) srow[j1] = e1 * inv;
    }
    // no syncthreads needed: each warp consumes only the sS rows it wrote

    // ---- A2 = attn @ v, then gating MLP -> scalar gate per (h, i) ----
    float b2v = b2[0];
    for (int task = w; task < NHEAD * NP1; task += 8) {
        int h = task & 3;
        int i = task >> 2;
        const float* arow = sS + (h * NP1 + i) * 52;
        float a2 = 0.f;
        #pragma unroll 7
        for (int jj = 0; jj < NP1; jj++)
            a2 = fmaf(arow[jj], sV[jj * DMODEL + h * HD + lane], a2);
        float t = sb1[lane];
        #pragma unroll
        for (int c = 0; c < HD; c++) {
            float ac = __shfl_sync(0xffffffffu, a2, c);
            t = fmaf(ac, sW1[c * HD + lane], t);
        }
        t = fmaxf(t, 0.f);
        float gp = warp_sum(t * sW2[lane]);
        if (lane == 0) sG[h * NP1 + i] = gp + b2v;
    }
    __syncthreads();

    // ---- em softmax + mask-normalize + gumbel-softmax (warp w = head h) ----
    if (w < NHEAD) {
        int h = w;
        int i0 = lane, i1 = lane + 32;
        bool has1 = (i1 < NP1);
        float g0 = sG[h * NP1 + i0];
        float g1 = has1 ? sG[h * NP1 + i1] : -INFINITY;
        float mx = warp_max(fmaxf(g0, g1));
        float e0 = expf(g0 - mx);
        float e1 = has1 ? expf(g1 - mx) : 0.f;
        float inv = 1.0f / warp_sum(e0 + e1);
        float em0 = e0 * inv * sM[i0];
        float em1 = has1 ? e1 * inv * sM[i1] : 0.f;
        float den = warp_sum(em0 + em1) + 1e-10f;
        em0 /= den;
        em1 /= den;
        size_t base = (((size_t)b * NN + j) * NHEAD + h) * NP1;
        out[base + i0] = em0;
        if (has1) out[base + i1] = em1;
        // gumbel-softmax (tau = 1)
        float l0 = logf(em0 + 1e-10f) + gumbel_noise((unsigned)(base + i0));
        float l1 = has1 ? (logf(em1 + 1e-10f) + gumbel_noise((unsigned)(base + i1))) : -INFINITY;
        float mx2 = warp_max(fmaxf(l0, l1));
        float t0 = expf(l0 - mx2);
        float t1 = has1 ? expf(l1 - mx2) : 0.f;
        float inv2 = 1.0f / warp_sum(t0 + t1);
        out[TOTALE + base + i0] = t0 * inv2;
        if (has1) out[TOTALE + base + i1] = t1 * inv2;
    }
}

// ---------------- launch ----------------
extern "C" void kernel_launch(void* const* d_in, const int* in_sizes, int n_in,
                              void* d_out, int out_size) {
    const float* x        = (const float*)d_in[0];
    const float* A        = (const float*)d_in[1];
    const float* amask    = (const float*)d_in[2];
    const float* W_embed  = (const float*)d_in[3];
    const float* b_embed  = (const float*)d_in[4];
    const float* ln_g     = (const float*)d_in[5];
    const float* ln_b     = (const float*)d_in[6];
    const float* W_qkv    = (const float*)d_in[7];
    const float* b_qkv    = (const float*)d_in[8];
    const float* W1       = (const float*)d_in[9];
    const float* b1       = (const float*)d_in[10];
    const float* W2       = (const float*)d_in[11];
    const float* b2       = (const float*)d_in[12];
    float* out = (float*)d_out;

    cudaFuncSetAttribute(k3_attn, cudaFuncAttributeMaxDynamicSharedMemorySize, SMEM3_BYTES);

    k1_pq<<<BSZ * NP1, 128>>>(x, amask, W_embed, b_embed);
    k2_embed_ln<<<BSZ * NN, 256>>>(A, amask, W_embed, ln_g, ln_b);
    k3_attn<<<BSZ * NN, 256, SMEM3_BYTES>>>(amask, W_qkv, b_qkv, W1, b1, W2, b2, out);
}

// round 3
// speedup vs baseline: 1.3503x; 1.3503x over previous
#include <cuda_runtime.h>

#define BSZ 128
#define NN 48
#define NP1 49
#define DM 32
#define DMODEL 128
#define NHEAD 4
#define HD 32
#define TOTALE (BSZ*NN*NHEAD*NP1)   /* 1204224 */

// ---------------- device scratch ----------------
__device__ float g_P[BSZ * NP1 * DMODEL];   // xn @ W_embed[0:32] + b_embed
__device__ float g_Q[BSZ * NN * DMODEL];    // x  @ W_embed[32:64]

// ---------------- helpers ----------------
__device__ __forceinline__ float warp_sum(float v) {
    #pragma unroll
    for (int o = 16; o > 0; o >>= 1) v += __shfl_xor_sync(0xffffffffu, v, o);
    return v;
}
__device__ __forceinline__ float warp_max(float v) {
    #pragma unroll
    for (int o = 16; o > 0; o >>= 1) v = fmaxf(v, __shfl_xor_sync(0xffffffffu, v, o));
    return v;
}
__device__ __forceinline__ unsigned rotl32(unsigned v, int r) {
    return (v << r) | (v >> (32 - r));
}
__device__ __forceinline__ unsigned long long fma2(unsigned long long a, unsigned long long b, unsigned long long c) {
    unsigned long long d;
    asm("fma.rn.f32x2 %0, %1, %2, %3;" : "=l"(d) : "l"(a), "l"(b), "l"(c));
    return d;
}
__device__ __forceinline__ unsigned long long pack2(float lo, float hi) {
    unsigned long long d;
    asm("mov.b64 %0, {%1, %2};" : "=l"(d) : "f"(lo), "f"(hi));
    return d;
}
__device__ __forceinline__ unsigned long long dup2(float v) {
    unsigned long long d;
    asm("mov.b64 %0, {%1, %1};" : "=l"(d) : "f"(v));
    return d;
}
__device__ __forceinline__ void unpack2(unsigned long long v, float& lo, float& hi) {
    asm("mov.b64 {%0, %1}, %2;" : "=f"(lo), "=f"(hi) : "l"(v));
}

// JAX partitionable-threefry gumbel noise (verified R2)
__device__ float gumbel_noise(unsigned idx) {
    unsigned x0 = 0u, x1 = idx;
    const unsigned ks0 = 0u, ks1 = 42u, ks2 = 0x1BD11BDAu ^ 0u ^ 42u;
    x0 += ks0; x1 += ks1;
#define TFR(r) { x0 += x1; x1 = rotl32(x1, r); x1 ^= x0; }
    TFR(13) TFR(15) TFR(26) TFR(6)   x0 += ks1; x1 += ks2 + 1u;
    TFR(17) TFR(29) TFR(16) TFR(24)  x0 += ks2; x1 += ks0 + 2u;
    TFR(13) TFR(15) TFR(26) TFR(6)   x0 += ks0; x1 += ks1 + 3u;
    TFR(17) TFR(29) TFR(16) TFR(24)  x0 += ks1; x1 += ks2 + 4u;
    TFR(13) TFR(15) TFR(26) TFR(6)   x0 += ks2; x1 += ks0 + 5u;
#undef TFR
    unsigned bits = x0 ^ x1;
    float u = __uint_as_float((bits >> 9) | 0x3f800000u) - 1.0f;
    float ex = -log1pf(-u);
    return -logf(ex);
}

// ---------------- kernel 1: P[b,i,:] and Q[b,j,:] ----------------
__global__ void k1_pq(const float* __restrict__ x,
                      const float* __restrict__ attn_mask,
                      const float* __restrict__ W_embed,
                      const float* __restrict__ b_embed) {
    int b = blockIdx.x / NP1;
    int n = blockIdx.x % NP1;
    int d = threadIdx.x;
    if (n == NN) {
        g_P[((size_t)b * NP1 + NN) * DMODEL + d] = b_embed[d];
        return;
    }
    __shared__ float am[NN];
    __shared__ float xm[DM];
    if (d < NN) am[d] = attn_mask[((size_t)b * NN + n) * NN + d];
    __syncthreads();
    float s = 0.f;
    #pragma unroll
    for (int c = 0; c < NN; c++) s += am[c];
    float ped = (s > 0.f) ? 1.f : 0.f;
    if (d < DM) xm[d] = x[((size_t)b * NN + n) * DM + d] * ped;
    __syncthreads();
    float p = b_embed[d];
    float q = 0.f;
    #pragma unroll
    for (int c = 0; c < DM; c++) {
        float xc = xm[c];
        p = fmaf(xc, W_embed[c * DMODEL + d], p);
        q = fmaf(xc, W_embed[(DM + c) * DMODEL + d], q);
    }
    g_P[((size_t)b * NP1 + n) * DMODEL + d] = p;
    g_Q[((size_t)b * NN + n) * DMODEL + d] = q;
}

// ---------------- fused kernel: E+LN -> qkv -> attention -> MLP -> em/gumbel ----------
// smem (floats). Phase aliasing: [E | W-tile] then [Q | V | KT]
#define OFF_E   0          /* 49*128 = 6272 */
#define OFF_WT  6272       /* 32*384 = 12288 (also holds sWA 4096 in E phase) */
#define OFF_Q   0          /* 6272 */
#define OFF_V   6272       /* 6272 */
#define OFF_KT  12544      /* 128*65 = 8320 -> ends 20864 */
#define PER     20864
#define OFF_M   (PER+0)      /* 64 */
#define OFF_BQ  (PER+64)     /* 384 */
#define OFF_W1  (PER+448)    /* 1024 */
#define OFF_B1  (PER+1472)   /* 32 */
#define OFF_W2  (PER+1504)   /* 32 */
#define OFF_G   (PER+1536)   /* 200 */
#define OFF_LG  (PER+1736)   /* 128 */
#define OFF_LB  (PER+1864)   /* 128 */
#define OFF_SP  (PER+1992)   /* 8*52 probs scratch */
#define OFF_SA  (PER+2408)   /* 8*32 a2 scratch */
#define SMEM3_FLOATS (PER+2664)
#define SMEM3_BYTES (SMEM3_FLOATS * 4)

__global__ void __launch_bounds__(256, 2) k3_attn(
    const float* __restrict__ A,
    const float* __restrict__ attn_mask,
    const float* __restrict__ W_embed,
    const float* __restrict__ ln_g,
    const float* __restrict__ ln_b,
    const float* __restrict__ W_qkv,
    const float* __restrict__ b_qkv,
    const float* __restrict__ W1,
    const float* __restrict__ b1,
    const float* __restrict__ W2,
    const float* __restrict__ b2,
    float* __restrict__ out) {
    extern __shared__ float sm[];
    int bj = blockIdx.x;
    int b = bj / NN, j = bj % NN;
    int tid = threadIdx.x, lane = tid & 31, w = tid >> 5;

    float* sE  = sm + OFF_E;
    float* wt  = sm + OFF_WT;
    float* sQ  = sm + OFF_Q;
    float* sV  = sm + OFF_V;
    float* sKT = sm + OFF_KT;
    float* sM  = sm + OFF_M;
    float* sBq = sm + OFF_BQ;
    float* sW1 = sm + OFF_W1;
    float* sb1 = sm + OFF_B1;
    float* sW2 = sm + OFF_W2;
    float* sG  = sm + OFF_G;
    float* sLG = sm + OFF_LG;
    float* sLB = sm + OFF_LB;

    // ---- persistent loads + sWA (W_embed rows 64..95) into wt region ----
    if (tid < NP1) sM[tid] = (tid < NN) ? attn_mask[((size_t)b * NN + j) * NN + tid] : 1.0f;
    for (int t = tid; t < 384; t += 256) sBq[t] = b_qkv[t];
    for (int t = tid; t < 1024; t += 256) sW1[t] = W1[t];
    if (tid < 32) { sb1[tid] = b1[tid]; sW2[tid] = W2[tid]; }
    if (tid >= 64 && tid < 192) { sLG[tid - 64] = ln_g[tid - 64]; sLB[tid - 64] = ln_b[tid - 64]; }
    for (int t = tid; t < DM * DMODEL; t += 256) wt[t] = W_embed[(2 * DM) * DMODEL + t];
    __syncthreads();

    // ---- E + LayerNorm into sE (per warp rows i = w, w+8, ...) ----
    {
        const float* Pb = g_P + (size_t)b * NP1 * DMODEL;
        const float* Qb = g_Q + ((size_t)b * NN + j) * DMODEL;
        float qv[4];
        #pragma unroll
        for (int r = 0; r < 4; r++) qv[r] = Qb[lane + 32 * r];

        for (int i = w; i < NP1; i += 8) {
            float a = 0.f;
            if (i < NN)
                a = A[(((size_t)b * NN + i) * NN + j) * DM + lane] * sM[i];
            float e[4];
            #pragma unroll
            for (int r = 0; r < 4; r++) e[r] = Pb[i * DMODEL + lane + 32 * r] + qv[r];
            #pragma unroll
            for (int c = 0; c < DM; c++) {
                float ac = __shfl_sync(0xffffffffu, a, c);
                #pragma unroll
                for (int r = 0; r < 4; r++) e[r] = fmaf(ac, wt[c * DMODEL + lane + 32 * r], e[r]);
            }
            float mu = warp_sum(e[0] + e[1] + e[2] + e[3]) * (1.0f / DMODEL);
            float sq = 0.f;
            #pragma unroll
            for (int r = 0; r < 4; r++) { float dv = e[r] - mu; sq += dv * dv; }
            float rs = rsqrtf(warp_sum(sq) * (1.0f / DMODEL) + 1e-5f);
            #pragma unroll
            for (int r = 0; r < 4; r++) {
                int d = lane + 32 * r;
                sE[i * DMODEL + d] = (e[r] - mu) * rs * sLG[d] + sLB[d];
            }
        }
    }
    __syncthreads();

    // ---- qkv GEMM with packed f32x2 FMAs ----
    // column pairs: col = 2*lane + 64*k2 (+0/+1), k2 = 0..5
    unsigned long long acc2[7][6];
    #pragma unroll
    for (int rr = 0; rr < 7; rr++)
        #pragma unroll
        for (int k2 = 0; k2 < 6; k2++) {
            int col = 2 * lane + 64 * k2;
            acc2[rr][k2] = pack2(sBq[col], sBq[col + 1]);  // bias folded into init
        }

    const unsigned long long* wt2 = (const unsigned long long*)wt;
    for (int d0 = 0; d0 < DMODEL; d0 += 32) {
        for (int t = tid; t < 32 * 384 / 4; t += 256)
            ((float4*)wt)[t] = ((const float4*)(W_qkv + (size_t)d0 * 384))[t];
        __syncthreads();
        #pragma unroll 4
        for (int dd = 0; dd < 32; dd++) {
            unsigned long long wv[6];
            #pragma unroll
            for (int k2 = 0; k2 < 6; k2++) wv[k2] = wt2[dd * 192 + lane + 32 * k2];
            #pragma unroll
            for (int rr = 0; rr < 7; rr++) {
                int row = w + 8 * rr;
                if (row < NP1) {
                    unsigned long long e2 = dup2(sE[row * DMODEL + d0 + dd]);
                    #pragma unroll
                    for (int k2 = 0; k2 < 6; k2++) acc2[rr][k2] = fma2(e2, wv[k2], acc2[rr][k2]);
                }
            }
        }
        __syncthreads();
    }

    // ---- zero-pad KT rows i=49..64, then scatter q/k^T/v (sE/wt now dead) ----
    for (int t = tid; t < 128 * 16; t += 256) {
        int krow = t >> 4, i = 49 + (t & 15);
        sKT[krow * 65 + i] = 0.f;
    }
    #pragma unroll
    for (int rr = 0; rr < 7; rr++) {
        int row = w + 8 * rr;
        if (row < NP1) {
            #pragma unroll
            for (int k2 = 0; k2 < 6; k2++) {
                float v0, v1;
                unpack2(acc2[rr][k2], v0, v1);
                int col = 2 * lane + 64 * k2;
                if (k2 < 2) {
                    sQ[row * DMODEL + col] = v0;
                    sQ[row * DMODEL + col + 1] = v1;
                } else if (k2 < 4) {
                    int kc = col - 128;
                    sKT[kc * 65 + row] = v0;
                    sKT[(kc + 1) * 65 + row] = v1;
                } else {
                    int vc = col - 256;
                    sV[row * DMODEL + vc] = v0;
                    sV[row * DMODEL + vc + 1] = v1;
                }
            }
        }
    }
    __syncthreads();

    // ---- fused scores -> softmax -> A2 -> gating MLP per (h,i) task ----
    const float scale = 0.1767766952966369f;  // 32^-0.5
    float b2v = b2[0];
    float* srow = sm + OFF_SP + w * 52;
    float* sa2  = sm + OFF_SA + w * 32;
    for (int task = w; task < NHEAD * NP1; task += 8) {
        int h = task & 3;
        int i = task >> 2;
        float mi = sM[i];
        int j0 = lane, j1 = lane + 32;
        bool has1 = (j1 < NP1);
        float s0 = 0.f, s1 = 0.f;
        #pragma unroll
        for (int d = 0; d < HD; d++) {
            float qv = sQ[i * DMODEL + h * HD + d];
            s0 = fmaf(qv, sKT[(h * HD + d) * 65 + j0], s0);
            s1 = fmaf(qv, sKT[(h * HD + d) * 65 + j1], s1);
        }
        float pm0 = mi * sM[j0];
        s0 = (pm0 > 0.f) ? s0 * scale : -1e9f;
        float pm1 = has1 ? mi * sM[j1] : 0.f;
        s1 = (has1 && pm1 > 0.f) ? s1 * scale : -1e9f;
        float mx = warp_max(fmaxf(s0, has1 ? s1 : -INFINITY));
        float e0 = expf(s0 - mx);
        float e1 = has1 ? expf(s1 - mx) : 0.f;
        float inv = 1.0f / warp_sum(e0 + e1);
        srow[j0] = e0 * inv;
        if (has1) srow[j1] = e1 * inv;
        __syncwarp();

        // A2 = probs @ V (d = lane)
        float a2 = 0.f;
        const float* vcol = sV + h * HD + lane;
        #pragma unroll 7
        for (int jj = 0; jj < NP1; jj++)
            a2 = fmaf(srow[jj], vcol[jj * DMODEL], a2);
        sa2[lane] = a2;
        __syncwarp();

        // gating MLP: relu(A2 @ W1 + b1) @ W2 + b2
        float t = sb1[lane];
        #pragma unroll
        for (int c = 0; c < HD; c++)
            t = fmaf(sa2[c], sW1[c * HD + lane], t);
        t = fmaxf(t, 0.f);
        float gp = warp_sum(t * sW2[lane]);
        if (lane == 0) sG[h * NP1 + i] = gp + b2v;
    }
    __syncthreads();

    // ---- em softmax + mask-normalize + gumbel-softmax (warp w = head h) ----
    if (w < NHEAD) {
        int h = w;
        int i0 = lane, i1 = lane + 32;
        bool has1 = (i1 < NP1);
        float g0 = sG[h * NP1 + i0];
        float g1 = has1 ? sG[h * NP1 + i1] : -INFINITY;
        float mx = warp_max(fmaxf(g0, g1));
        float e0 = expf(g0 - mx);
        float e1 = has1 ? expf(g1 - mx) : 0.f;
        float inv = 1.0f / warp_sum(e0 + e1);
        float em0 = e0 * inv * sM[i0];
        float em1 = has1 ? e1 * inv * sM[i1] : 0.f;
        float den = warp_sum(em0 + em1) + 1e-10f;
        em0 /= den;
        em1 /= den;
        size_t base = (((size_t)b * NN + j) * NHEAD + h) * NP1;
        out[base + i0] = em0;
        if (has1) out[base + i1] = em1;
        float l0 = logf(em0 + 1e-10f) + gumbel_noise((unsigned)(base + i0));
        float l1 = has1 ? (logf(em1 + 1e-10f) + gumbel_noise((unsigned)(base + i1))) : -INFINITY;
        float mx2 = warp_max(fmaxf(l0, l1));
        float t0 = expf(l0 - mx2);
        float t1 = has1 ? expf(l1 - mx2) : 0.f;
        float inv2 = 1.0f / warp_sum(t0 + t1);
        out[TOTALE + base + i0] = t0 * inv2;
        if (has1) out[TOTALE + base + i1] = t1 * inv2;
    }
}

// ---------------- launch ----------------
extern "C" void kernel_launch(void* const* d_in, const int* in_sizes, int n_in,
                              void* d_out, int out_size) {
    const float* x        = (const float*)d_in[0];
    const float* A        = (const float*)d_in[1];
    const float* amask    = (const float*)d_in[2];
    const float* W_embed  = (const float*)d_in[3];
    const float* b_embed  = (const float*)d_in[4];
    const float* ln_g     = (const float*)d_in[5];
    const float* ln_b     = (const float*)d_in[6];
    const float* W_qkv    = (const float*)d_in[7];
    const float* b_qkv    = (const float*)d_in[8];
    const float* W1       = (const float*)d_in[9];
    const float* b1       = (const float*)d_in[10];
    const float* W2       = (const float*)d_in[11];
    const float* b2       = (const float*)d_in[12];
    float* out = (float*)d_out;

    cudaFuncSetAttribute(k3_attn, cudaFuncAttributeMaxDynamicSharedMemorySize, SMEM3_BYTES);

    k1_pq<<<BSZ * NP1, 128>>>(x, amask, W_embed, b_embed);
    k3_attn<<<BSZ * NN, 256, SMEM3_BYTES>>>(A, amask, W_embed, ln_g, ln_b,
                                            W_qkv, b_qkv, W1, b1, W2, b2, out);
}

// round 4
// speedup vs baseline: 1.5376x; 1.1388x over previous
#include <cuda_runtime.h>

#define BSZ 128
#define NN 48
#define NP1 49
#define DM 32
#define DMODEL 128
#define NHEAD 4
#define HD 32
#define TOTALE (BSZ*NN*NHEAD*NP1)   /* 1204224 */

// ---------------- device scratch ----------------
__device__ float g_P[BSZ * NP1 * DMODEL];   // xn @ W_embed[0:32] + b_embed
__device__ float g_Q[BSZ * NN * DMODEL];    // x  @ W_embed[32:64]

// ---------------- helpers ----------------
__device__ __forceinline__ float warp_sum(float v) {
    #pragma unroll
    for (int o = 16; o > 0; o >>= 1) v += __shfl_xor_sync(0xffffffffu, v, o);
    return v;
}
__device__ __forceinline__ float warp_max(float v) {
    #pragma unroll
    for (int o = 16; o > 0; o >>= 1) v = fmaxf(v, __shfl_xor_sync(0xffffffffu, v, o));
    return v;
}
__device__ __forceinline__ unsigned rotl32(unsigned v, int r) {
    return (v << r) | (v >> (32 - r));
}
__device__ __forceinline__ unsigned long long fma2(unsigned long long a, unsigned long long b, unsigned long long c) {
    unsigned long long d;
    asm("fma.rn.f32x2 %0, %1, %2, %3;" : "=l"(d) : "l"(a), "l"(b), "l"(c));
    return d;
}
__device__ __forceinline__ unsigned long long pack2(float lo, float hi) {
    unsigned long long d;
    asm("mov.b64 %0, {%1, %2};" : "=l"(d) : "f"(lo), "f"(hi));
    return d;
}
__device__ __forceinline__ unsigned long long dup2(float v) {
    unsigned long long d;
    asm("mov.b64 %0, {%1, %1};" : "=l"(d) : "f"(v));
    return d;
}
__device__ __forceinline__ void unpack2(unsigned long long v, float& lo, float& hi) {
    asm("mov.b64 {%0, %1}, %2;" : "=f"(lo), "=f"(hi) : "l"(v));
}

// JAX partitionable-threefry gumbel noise (verified R2/R3)
__device__ float gumbel_noise(unsigned idx) {
    unsigned x0 = 0u, x1 = idx;
    const unsigned ks0 = 0u, ks1 = 42u, ks2 = 0x1BD11BDAu ^ 0u ^ 42u;
    x0 += ks0; x1 += ks1;
#define TFR(r) { x0 += x1; x1 = rotl32(x1, r); x1 ^= x0; }
    TFR(13) TFR(15) TFR(26) TFR(6)   x0 += ks1; x1 += ks2 + 1u;
    TFR(17) TFR(29) TFR(16) TFR(24)  x0 += ks2; x1 += ks0 + 2u;
    TFR(13) TFR(15) TFR(26) TFR(6)   x0 += ks0; x1 += ks1 + 3u;
    TFR(17) TFR(29) TFR(16) TFR(24)  x0 += ks1; x1 += ks2 + 4u;
    TFR(13) TFR(15) TFR(26) TFR(6)   x0 += ks2; x1 += ks0 + 5u;
#undef TFR
    unsigned bits = x0 ^ x1;
    float u = __uint_as_float((bits >> 9) | 0x3f800000u) - 1.0f;
    float ex = -log1pf(-u);
    return -logf(ex);
}

// ---------------- kernel 1: P[b,i,:] and Q[b,j,:] ----------------
__global__ void k1_pq(const float* __restrict__ x,
                      const float* __restrict__ attn_mask,
                      const float* __restrict__ W_embed,
                      const float* __restrict__ b_embed) {
    int b = blockIdx.x / NP1;
    int n = blockIdx.x % NP1;
    int d = threadIdx.x;
    if (n == NN) {
        g_P[((size_t)b * NP1 + NN) * DMODEL + d] = b_embed[d];
        return;
    }
    __shared__ float am[NN];
    __shared__ float xm[DM];
    if (d < NN) am[d] = attn_mask[((size_t)b * NN + n) * NN + d];
    __syncthreads();
    float s = 0.f;
    #pragma unroll
    for (int c = 0; c < NN; c++) s += am[c];
    float ped = (s > 0.f) ? 1.f : 0.f;
    if (d < DM) xm[d] = x[((size_t)b * NN + n) * DM + d] * ped;
    __syncthreads();
    float p = b_embed[d];
    float q = 0.f;
    #pragma unroll
    for (int c = 0; c < DM; c++) {
        float xc = xm[c];
        p = fmaf(xc, W_embed[c * DMODEL + d], p);
        q = fmaf(xc, W_embed[(DM + c) * DMODEL + d], q);
    }
    g_P[((size_t)b * NP1 + n) * DMODEL + d] = p;
    g_Q[((size_t)b * NN + n) * DMODEL + d] = q;
}

// ---------------- fused kernel ----------------
// smem (floats). Phase A: [sE 6272 | wt 12288] ; Phase B: [sQ 6272 | sV 6272 | sKT 128*52=6656]
#define OFF_E   0
#define OFF_WT  6272
#define OFF_Q   0
#define OFF_V   6272
#define KTSTR   52
#define OFF_KT  12544          /* 12544..19200 */
#define PER     19200
#define OFF_M   (PER+0)        /* 64 */
#define OFF_BQ  (PER+64)       /* 384 */
#define OFF_W1  (PER+448)      /* 1024 */
#define OFF_B1  (PER+1472)     /* 32 */
#define OFF_W2  (PER+1504)     /* 32 */
#define OFF_G   (PER+1536)     /* 200 */
#define OFF_LG  (PER+1736)     /* 128 */
#define OFF_LB  (PER+1864)     /* 128 */
#define SMEM3_FLOATS (PER+1992)
#define SMEM3_BYTES (SMEM3_FLOATS * 4)

__global__ void __launch_bounds__(256, 2) k3_attn(
    const float* __restrict__ A,
    const float* __restrict__ attn_mask,
    const float* __restrict__ W_embed,
    const float* __restrict__ ln_g,
    const float* __restrict__ ln_b,
    const float* __restrict__ W_qkv,
    const float* __restrict__ b_qkv,
    const float* __restrict__ W1,
    const float* __restrict__ b1,
    const float* __restrict__ W2,
    const float* __restrict__ b2,
    float* __restrict__ out) {
    extern __shared__ float sm[];
    int bj = blockIdx.x;
    int b = bj / NN, j = bj % NN;
    int tid = threadIdx.x, lane = tid & 31, w = tid >> 5;

    float* sE  = sm + OFF_E;
    float* wt  = sm + OFF_WT;
    float* sQ  = sm + OFF_Q;
    float* sV  = sm + OFF_V;
    float* sKT = sm + OFF_KT;
    float* sM  = sm + OFF_M;
    float* sBq = sm + OFF_BQ;
    float* sW1 = sm + OFF_W1;
    float* sb1 = sm + OFF_B1;
    float* sW2 = sm + OFF_W2;
    float* sG  = sm + OFF_G;
    float* sLG = sm + OFF_LG;
    float* sLB = sm + OFF_LB;

    // ---- persistent loads + sWA (W_embed rows 64..95) into wt region ----
    if (tid < 64) sM[tid] = (tid < NN) ? attn_mask[((size_t)b * NN + j) * NN + tid]
                                       : (tid == NN ? 1.0f : 0.0f);
    for (int t = tid; t < 384; t += 256) sBq[t] = b_qkv[t];
    for (int t = tid; t < 1024; t += 256) sW1[t] = W1[t];
    if (tid < 32) { sb1[tid] = b1[tid]; sW2[tid] = W2[tid]; }
    if (tid >= 64 && tid < 192) { sLG[tid - 64] = ln_g[tid - 64]; sLB[tid - 64] = ln_b[tid - 64]; }
    for (int t = tid; t < DM * DMODEL; t += 256) wt[t] = W_embed[(2 * DM) * DMODEL + t];
    __syncthreads();

    // ---- E + LayerNorm into sE, f32x2 over column pairs ----
    {
        const float2* Pb2 = (const float2*)(g_P + (size_t)b * NP1 * DMODEL);
        const float2* Qb2 = (const float2*)(g_Q + ((size_t)b * NN + j) * DMODEL);
        const unsigned long long* wt2 = (const unsigned long long*)wt;
        float2 qva = Qb2[lane];          // cols 2l,2l+1
        float2 qvb = Qb2[32 + lane];     // cols 64+2l, 64+2l+1
        // ln params for this lane's 4 columns
        float lg0 = sLG[2*lane], lg1 = sLG[2*lane+1], lg2 = sLG[64+2*lane], lg3 = sLG[64+2*lane+1];
        float lb0 = sLB[2*lane], lb1 = sLB[2*lane+1], lb2 = sLB[64+2*lane], lb3 = sLB[64+2*lane+1];

        for (int i = w; i < NP1; i += 8) {
            float a = 0.f;
            if (i < NN)
                a = A[(((size_t)b * NN + i) * NN + j) * DM + lane] * sM[i];
            float2 p0 = Pb2[i * 64 + lane];
            float2 p1 = Pb2[i * 64 + 32 + lane];
            unsigned long long e0 = pack2(p0.x + qva.x, p0.y + qva.y);
            unsigned long long e1 = pack2(p1.x + qvb.x, p1.y + qvb.y);
            #pragma unroll
            for (int c = 0; c < DM; c++) {
                unsigned long long ac = dup2(__shfl_sync(0xffffffffu, a, c));
                e0 = fma2(ac, wt2[c * 64 + lane], e0);
                e1 = fma2(ac, wt2[c * 64 + 32 + lane], e1);
            }
            float v0, v1, v2, v3;
            unpack2(e0, v0, v1); unpack2(e1, v2, v3);
            float mu = warp_sum(v0 + v1 + v2 + v3) * (1.0f / DMODEL);
            float d0 = v0 - mu, d1 = v1 - mu, d2 = v2 - mu, d3 = v3 - mu;
            float rs = rsqrtf(warp_sum(d0*d0 + d1*d1 + d2*d2 + d3*d3) * (1.0f / DMODEL) + 1e-5f);
            float2* dst = (float2*)(sE + i * DMODEL);
            dst[lane]      = make_float2(d0 * rs * lg0 + lb0, d1 * rs * lg1 + lb1);
            dst[32 + lane] = make_float2(d2 * rs * lg2 + lb2, d3 * rs * lg3 + lb3);
        }
    }
    __syncthreads();

    // ---- qkv GEMM: f32x2 accs, cols = 128*k4 + 4*lane + {0..3} ----
    unsigned long long acc2[7][6];
    #pragma unroll
    for (int rr = 0; rr < 7; rr++)
        #pragma unroll
        for (int k4 = 0; k4 < 3; k4++) {
            int col = 128 * k4 + 4 * lane;
            acc2[rr][2*k4]   = pack2(sBq[col],     sBq[col + 1]);
            acc2[rr][2*k4+1] = pack2(sBq[col + 2], sBq[col + 3]);
        }

    for (int d0 = 0; d0 < DMODEL; d0 += 32) {
        for (int t = tid; t < 32 * 384 / 4; t += 256)
            ((float4*)wt)[t] = ((const float4*)(W_qkv + (size_t)d0 * 384))[t];
        __syncthreads();
        // preload E operands for this tile: one scalar per row per lane
        float eReg[7];
        #pragma unroll
        for (int rr = 0; rr < 7; rr++) {
            int row = w + 8 * rr;
            eReg[rr] = (row < NP1) ? sE[row * DMODEL + d0 + lane] : 0.f;
        }
        #pragma unroll 2
        for (int dd = 0; dd < 32; dd++) {
            ulonglong2 wv[3];
            #pragma unroll
            for (int k4 = 0; k4 < 3; k4++)
                wv[k4] = ((const ulonglong2*)(wt + dd * 384 + 128 * k4))[lane];
            #pragma unroll
            for (int rr = 0; rr < 7; rr++) {
                unsigned long long e2 = dup2(__shfl_sync(0xffffffffu, eReg[rr], dd));
                #pragma unroll
                for (int k4 = 0; k4 < 3; k4++) {
                    acc2[rr][2*k4]   = fma2(e2, wv[k4].x, acc2[rr][2*k4]);
                    acc2[rr][2*k4+1] = fma2(e2, wv[k4].y, acc2[rr][2*k4+1]);
                }
            }
        }
        __syncthreads();
    }

    // ---- zero KT pad cols j=49..51, scatter q / k^T / v ----
    for (int t = tid; t < 128 * 3; t += 256) {
        int d = t / 3, jz = 49 + (t % 3);
        sKT[d * KTSTR + jz] = 0.f;
    }
    #pragma unroll
    for (int rr = 0; rr < 7; rr++) {
        int row = w + 8 * rr;
        if (row < NP1) {
            float q0,q1,q2,q3, k0,k1,k2,k3, v0,v1,v2,v3;
            unpack2(acc2[rr][0], q0, q1); unpack2(acc2[rr][1], q2, q3);
            unpack2(acc2[rr][2], k0, k1); unpack2(acc2[rr][3], k2, k3);
            unpack2(acc2[rr][4], v0, v1); unpack2(acc2[rr][5], v2, v3);
            ((float4*)(sQ + row * DMODEL))[lane] = make_float4(q0, q1, q2, q3);
            ((float4*)(sV + row * DMODEL))[lane] = make_float4(v0, v1, v2, v3);
            int kd = 4 * lane;
            sKT[kd * KTSTR + row] = k0;
            sKT[(kd + 1) * KTSTR + row] = k1;
            sKT[(kd + 2) * KTSTR + row] = k2;
            sKT[(kd + 3) * KTSTR + row] = k3;
        }
    }
    __syncthreads();

    // ---- attention: 28 blocks of (head h, 7 i-rows). probs stay in registers ----
    const float scale = 0.1767766952966369f;  // 32^-0.5
    float b2v = b2[0];
    float w1r[DM];
    #pragma unroll
    for (int c = 0; c < DM; c++) w1r[c] = sW1[c * HD + lane];
    float b1r = sb1[lane], w2r = sW2[lane];
    float m0 = sM[2 * lane], m1 = sM[2 * lane + 1];
    bool vj0 = (2 * lane) < NP1;       // j = 2l valid
    bool vj1 = (2 * lane + 1) < NP1;   // j = 2l+1 valid

    for (int blk = w; blk < 28; blk += 8) {
        int h = blk & 3;
        int ib = blk >> 2;          // 0..6
        int ibase = ib * 7;
        // q preload: qreg[r][d=lane]
        float qreg[7], mi[7];
        #pragma unroll
        for (int r = 0; r < 7; r++) {
            qreg[r] = sQ[(ibase + r) * DMODEL + h * HD + lane];
            mi[r] = sM[ibase + r];
        }
        // scores: s2[r] over j-pairs (2l, 2l+1)
        unsigned long long s2[7];
        #pragma unroll
        for (int r = 0; r < 7; r++) s2[r] = 0ull;
        const float* ktb = sKT + (h * HD) * KTSTR + 2 * lane;
        #pragma unroll 4
        for (int d = 0; d < HD; d++) {
            unsigned long long kv2 = (lane < 26) ? *(const unsigned long long*)(ktb + d * KTSTR) : 0ull;
            #pragma unroll
            for (int r = 0; r < 7; r++) {
                unsigned long long qd = dup2(__shfl_sync(0xffffffffu, qreg[r], d));
                s2[r] = fma2(qd, kv2, s2[r]);
            }
        }
        // softmax per row -> p2[r] in registers
        unsigned long long p2[7];
        #pragma unroll
        for (int r = 0; r < 7; r++) {
            float s0, s1;
            unpack2(s2[r], s0, s1);
            float pm0 = mi[r] * m0, pm1 = mi[r] * m1;
            s0 = vj0 ? ((pm0 > 0.f) ? s0 * scale : -1e9f) : -INFINITY;
            s1 = vj1 ? ((pm1 > 0.f) ? s1 * scale : -1e9f) : -INFINITY;
            float mx = warp_max(fmaxf(s0, s1));
            float e0 = vj0 ? expf(s0 - mx) : 0.f;
            float e1 = vj1 ? expf(s1 - mx) : 0.f;
            float inv = 1.0f / warp_sum(e0 + e1);
            p2[r] = pack2(e0 * inv, e1 * inv);
        }
        // A2 = probs @ V : packed accumulate over j-pairs, lane = d
        unsigned long long a2acc[7];
        #pragma unroll
        for (int r = 0; r < 7; r++) a2acc[r] = 0ull;
        const float* vb = sV + h * HD + lane;
        #pragma unroll 5
        for (int jp = 0; jp < 25; jp++) {
            unsigned long long v2 = pack2(vb[(2 * jp) * DMODEL], vb[(2 * jp + 1) * DMODEL]);
            #pragma unroll
            for (int r = 0; r < 7; r++) {
                unsigned long long pp = __shfl_sync(0xffffffffu, p2[r], jp);
                a2acc[r] = fma2(pp, v2, a2acc[r]);
            }
        }
        // MLP per row: relu(A2 @ W1 + b1) @ W2 + b2
        #pragma unroll
        for (int r = 0; r < 7; r++) {
            float alo, ahi;
            unpack2(a2acc[r], alo, ahi);
            float a2 = alo + ahi;          // lane = d component of A2 row
            float t = b1r;
            #pragma unroll
            for (int c = 0; c < DM; c++)
                t = fmaf(__shfl_sync(0xffffffffu, a2, c), w1r[c], t);
            t = fmaxf(t, 0.f);
            float gp = warp_sum(t * w2r);
            if (lane == 0) sG[h * NP1 + ibase + r] = gp + b2v;
        }
    }
    __syncthreads();

    // ---- em softmax + mask-normalize + gumbel-softmax (warp w = head h) ----
    if (w < NHEAD) {
        int h = w;
        int i0 = lane, i1 = lane + 32;
        bool has1 = (i1 < NP1);
        float g0 = sG[h * NP1 + i0];
        float g1 = has1 ? sG[h * NP1 + i1] : -INFINITY;
        float mx = warp_max(fmaxf(g0, g1));
        float e0 = expf(g0 - mx);
        float e1 = has1 ? expf(g1 - mx) : 0.f;
        float inv = 1.0f / warp_sum(e0 + e1);
        float em0 = e0 * inv * sM[i0];
        float em1 = has1 ? e1 * inv * sM[i1] : 0.f;
        float den = warp_sum(em0 + em1) + 1e-10f;
        em0 /= den;
        em1 /= den;
        size_t base = (((size_t)b * NN + j) * NHEAD + h) * NP1;
        out[base + i0] = em0;
        if (has1) out[base + i1] = em1;
        float l0 = logf(em0 + 1e-10f) + gumbel_noise((unsigned)(base + i0));
        float l1 = has1 ? (logf(em1 + 1e-10f) + gumbel_noise((unsigned)(base + i1))) : -INFINITY;
        float mx2 = warp_max(fmaxf(l0, l1));
        float t0 = expf(l0 - mx2);
        float t1 = has1 ? expf(l1 - mx2) : 0.f;
        float inv2 = 1.0f / warp_sum(t0 + t1);
        out[TOTALE + base + i0] = t0 * inv2;
        if (has1) out[TOTALE + base + i1] = t1 * inv2;
    }
}

// ---------------- launch ----------------
extern "C" void kernel_launch(void* const* d_in, const int* in_sizes, int n_in,
                              void* d_out, int out_size) {
    const float* x        = (const float*)d_in[0];
    const float* A        = (const float*)d_in[1];
    const float* amask    = (const float*)d_in[2];
    const float* W_embed  = (const float*)d_in[3];
    const float* b_embed  = (const float*)d_in[4];
    const float* ln_g     = (const float*)d_in[5];
    const float* ln_b     = (const float*)d_in[6];
    const float* W_qkv    = (const float*)d_in[7];
    const float* b_qkv    = (const float*)d_in[8];
    const float* W1       = (const float*)d_in[9];
    const float* b1       = (const float*)d_in[10];
    const float* W2       = (const float*)d_in[11];
    const float* b2       = (const float*)d_in[12];
    float* out = (float*)d_out;

    cudaFuncSetAttribute(k3_attn, cudaFuncAttributeMaxDynamicSharedMemorySize, SMEM3_BYTES);

    k1_pq<<<BSZ * NP1, 128>>>(x, amask, W_embed, b_embed);
    k3_attn<<<BSZ * NN, 256, SMEM3_BYTES>>>(A, amask, W_embed, ln_g, ln_b,
                                            W_qkv, b_qkv, W1, b1, W2, b2, out);
}

// round 5
// speedup vs baseline: 1.7278x; 1.1237x over previous
#include <cuda_runtime.h>

#define BSZ 128
#define NN 48
#define NP1 49
#define DM 32
#define DMODEL 128
#define NHEAD 4
#define HD 32
#define TOTALE (BSZ*NN*NHEAD*NP1)   /* 1204224 */

typedef unsigned long long ull;

// ---------------- device scratch ----------------
__device__ float g_P[BSZ * NP1 * DMODEL];
__device__ float g_Q[BSZ * NN * DMODEL];

// ---------------- helpers ----------------
__device__ __forceinline__ float warp_sum(float v) {
    #pragma unroll
    for (int o = 16; o > 0; o >>= 1) v += __shfl_xor_sync(0xffffffffu, v, o);
    return v;
}
__device__ __forceinline__ float warp_max(float v) {
    #pragma unroll
    for (int o = 16; o > 0; o >>= 1) v = fmaxf(v, __shfl_xor_sync(0xffffffffu, v, o));
    return v;
}
__device__ __forceinline__ unsigned rotl32(unsigned v, int r) {
    return (v << r) | (v >> (32 - r));
}
__device__ __forceinline__ ull fma2(ull a, ull b, ull c) {
    ull d;
    asm("fma.rn.f32x2 %0, %1, %2, %3;" : "=l"(d) : "l"(a), "l"(b), "l"(c));
    return d;
}
__device__ __forceinline__ ull pack2(float lo, float hi) {
    ull d;
    asm("mov.b64 %0, {%1, %2};" : "=l"(d) : "f"(lo), "f"(hi));
    return d;
}
__device__ __forceinline__ ull dup2(float v) {
    ull d;
    asm("mov.b64 %0, {%1, %1};" : "=l"(d) : "f"(v));
    return d;
}
__device__ __forceinline__ void unpack2(ull v, float& lo, float& hi) {
    asm("mov.b64 {%0, %1}, %2;" : "=f"(lo), "=f"(hi) : "l"(v));
}

// JAX partitionable-threefry gumbel noise (verified R2-R4)
__device__ float gumbel_noise(unsigned idx) {
    unsigned x0 = 0u, x1 = idx;
    const unsigned ks0 = 0u, ks1 = 42u, ks2 = 0x1BD11BDAu ^ 0u ^ 42u;
    x0 += ks0; x1 += ks1;
#define TFR(r) { x0 += x1; x1 = rotl32(x1, r); x1 ^= x0; }
    TFR(13) TFR(15) TFR(26) TFR(6)   x0 += ks1; x1 += ks2 + 1u;
    TFR(17) TFR(29) TFR(16) TFR(24)  x0 += ks2; x1 += ks0 + 2u;
    TFR(13) TFR(15) TFR(26) TFR(6)   x0 += ks0; x1 += ks1 + 3u;
    TFR(17) TFR(29) TFR(16) TFR(24)  x0 += ks1; x1 += ks2 + 4u;
    TFR(13) TFR(15) TFR(26) TFR(6)   x0 += ks2; x1 += ks0 + 5u;
#undef TFR
    unsigned bits = x0 ^ x1;
    float u = __uint_as_float((bits >> 9) | 0x3f800000u) - 1.0f;
    float ex = -log1pf(-u);
    return -logf(ex);
}

// ---------------- kernel 1 ----------------
__global__ void k1_pq(const float* __restrict__ x,
                      const float* __restrict__ attn_mask,
                      const float* __restrict__ W_embed,
                      const float* __restrict__ b_embed) {
    int b = blockIdx.x / NP1;
    int n = blockIdx.x % NP1;
    int d = threadIdx.x;
    if (n == NN) {
        g_P[((size_t)b * NP1 + NN) * DMODEL + d] = b_embed[d];
        return;
    }
    __shared__ float am[NN];
    __shared__ float xm[DM];
    if (d < NN) am[d] = attn_mask[((size_t)b * NN + n) * NN + d];
    __syncthreads();
    float s = 0.f;
    #pragma unroll
    for (int c = 0; c < NN; c++) s += am[c];
    float ped = (s > 0.f) ? 1.f : 0.f;
    if (d < DM) xm[d] = x[((size_t)b * NN + n) * DM + d] * ped;
    __syncthreads();
    float p = b_embed[d];
    float q = 0.f;
    #pragma unroll
    for (int c = 0; c < DM; c++) {
        float xc = xm[c];
        p = fmaf(xc, W_embed[c * DMODEL + d], p);
        q = fmaf(xc, W_embed[(DM + c) * DMODEL + d], q);
    }
    g_P[((size_t)b * NP1 + n) * DMODEL + d] = p;
    g_Q[((size_t)b * NN + n) * DMODEL + d] = q;
}

// ---------------- fused kernel smem layout (floats) ----------------
#define OFF_E   0          /* phase A/B: 49*128 = 6272 */
#define OFF_WA  6272       /* phase A: W_embed rows 64..95, 4096 */
#define OFF_AE  10368      /* phase A: a-staging 56*32 = 1792 */
#define OFF_WT  6272       /* phase B: W_qkv tile 32*384 = 12288 -> ends 18560 */
#define OFF_Q   0          /* phase C: 6272 */
#define OFF_V   6272       /* phase C: 6272 */
#define KTSTR   52
#define OFF_KT  12544      /* phase C: 128*52 = 6656 -> ends 19200 */
#define OFF_SP  19200      /* probs scratch 8*7*52 = 2912 -> 22112 */
#define OFF_SA2 22112      /* a2 scratch 8*32 = 256 -> 22368 */
#define PER     22368
#define OFF_M   (PER+0)
#define OFF_BQ  (PER+64)
#define OFF_W1  (PER+448)
#define OFF_B1  (PER+1472)
#define OFF_W2  (PER+1504)
#define OFF_G   (PER+1536)
#define OFF_LG  (PER+1736)
#define OFF_LB  (PER+1864)
#define SMEM3_FLOATS (PER+1992)
#define SMEM3_BYTES (SMEM3_FLOATS * 4)

__global__ void __launch_bounds__(256, 2) k3_attn(
    const float* __restrict__ A,
    const float* __restrict__ attn_mask,
    const float* __restrict__ W_embed,
    const float* __restrict__ ln_g,
    const float* __restrict__ ln_b,
    const float* __restrict__ W_qkv,
    const float* __restrict__ b_qkv,
    const float* __restrict__ W1,
    const float* __restrict__ b1,
    const float* __restrict__ W2,
    const float* __restrict__ b2,
    float* __restrict__ out) {
    extern __shared__ float sm[];
    int bj = blockIdx.x;
    int b = bj / NN, j = bj % NN;
    int tid = threadIdx.x, lane = tid & 31, w = tid >> 5;
    bool wzero = (w == 0);

    float* sE  = sm + OFF_E;
    float* sWA = sm + OFF_WA;
    float* sAE = sm + OFF_AE;
    float* wt  = sm + OFF_WT;
    float* sQ  = sm + OFF_Q;
    float* sV  = sm + OFF_V;
    float* sKT = sm + OFF_KT;
    float* sP  = sm + OFF_SP;
    float* sA2 = sm + OFF_SA2;
    float* sM  = sm + OFF_M;
    float* sBq = sm + OFF_BQ;
    float* sW1 = sm + OFF_W1;
    float* sb1 = sm + OFF_B1;
    float* sW2 = sm + OFF_W2;
    float* sG  = sm + OFF_G;
    float* sLG = sm + OFF_LG;
    float* sLB = sm + OFF_LB;

    // ---- persistent loads ----
    if (tid < 64) sM[tid] = (tid < NN) ? attn_mask[((size_t)b * NN + j) * NN + tid]
                                       : (tid == NN ? 1.0f : 0.0f);
    for (int t = tid; t < 384; t += 256) sBq[t] = b_qkv[t];
    for (int t = tid; t < 1024; t += 256) sW1[t] = W1[t];
    if (tid < 32) { sb1[tid] = b1[tid]; sW2[tid] = W2[tid]; }
    if (tid >= 64 && tid < 192) { sLG[tid - 64] = ln_g[tid - 64]; sLB[tid - 64] = ln_b[tid - 64]; }
    for (int t = tid; t < DM * DMODEL; t += 256) sWA[t] = W_embed[(2 * DM) * DMODEL + t];
    __syncthreads();

    // ================= E + LayerNorm (row-batched per warp) =================
    {
        // stage masked A rows: lane = c
        #pragma unroll
        for (int rr = 0; rr < 7; rr++) {
            int row = w + 8 * rr;
            if (rr < 6 || wzero) {
                float a = 0.f;
                if (row < NN)
                    a = A[(((size_t)b * NN + row) * NN + j) * DM + lane] * sM[row];
                sAE[(w * 7 + rr) * DM + lane] = a;
            }
        }
        __syncwarp();

        const float2* Pb2 = (const float2*)(g_P + (size_t)b * NP1 * DMODEL);
        const float2* Qb2 = (const float2*)(g_Q + ((size_t)b * NN + j) * DMODEL);
        const ull* wt2 = (const ull*)sWA;
        float2 qva = Qb2[lane];
        float2 qvb = Qb2[32 + lane];
        float lg0 = sLG[2*lane], lg1 = sLG[2*lane+1], lg2 = sLG[64+2*lane], lg3 = sLG[64+2*lane+1];
        float lb0 = sLB[2*lane], lb1 = sLB[2*lane+1], lb2 = sLB[64+2*lane], lb3 = sLB[64+2*lane+1];

        ull e0[7], e1[7];
        #pragma unroll
        for (int rr = 0; rr < 7; rr++) {
            int row = w + 8 * rr;
            if (rr < 6 || wzero) {
                float2 p0 = Pb2[row * 64 + lane];
                float2 p1 = Pb2[row * 64 + 32 + lane];
                e0[rr] = pack2(p0.x + qva.x, p0.y + qva.y);
                e1[rr] = pack2(p1.x + qvb.x, p1.y + qvb.y);
            }
        }
        // c-loop over all rows at once (W_embed read once per warp)
        #pragma unroll 2
        for (int cg = 0; cg < 8; cg++) {
            float4 a4[7];
            #pragma unroll
            for (int rr = 0; rr < 7; rr++)
                if (rr < 6 || wzero)
                    a4[rr] = *(const float4*)(sAE + (w * 7 + rr) * DM + 4 * cg);
            #pragma unroll
            for (int t = 0; t < 4; t++) {
                int c = 4 * cg + t;
                ull wv0 = wt2[c * 64 + lane];
                ull wv1 = wt2[c * 64 + 32 + lane];
                #pragma unroll
                for (int rr = 0; rr < 7; rr++) {
                    if (rr < 6 || wzero) {
                        ull ac = dup2(((const float*)&a4[rr])[t]);
                        e0[rr] = fma2(ac, wv0, e0[rr]);
                        e1[rr] = fma2(ac, wv1, e1[rr]);
                    }
                }
            }
        }
        // LayerNorm + store
        #pragma unroll
        for (int rr = 0; rr < 7; rr++) {
            int row = w + 8 * rr;
            if (rr < 6 || wzero) {
                float v0, v1, v2, v3;
                unpack2(e0[rr], v0, v1); unpack2(e1[rr], v2, v3);
                float mu = warp_sum(v0 + v1 + v2 + v3) * (1.0f / DMODEL);
                float d0 = v0 - mu, d1 = v1 - mu, d2 = v2 - mu, d3 = v3 - mu;
                float rs = rsqrtf(warp_sum(d0*d0 + d1*d1 + d2*d2 + d3*d3) * (1.0f / DMODEL) + 1e-5f);
                float2* dst = (float2*)(sE + row * DMODEL);
                dst[lane]      = make_float2(d0 * rs * lg0 + lb0, d1 * rs * lg1 + lb1);
                dst[32 + lane] = make_float2(d2 * rs * lg2 + lb2, d3 * rs * lg3 + lb3);
            }
        }
    }
    __syncthreads();

    // ================= qkv GEMM (lane = col-quad, rows per warp) =================
    ull acc2[7][6];
    #pragma unroll
    for (int rr = 0; rr < 7; rr++) {
        if (rr < 6 || wzero) {
            #pragma unroll
            for (int k4 = 0; k4 < 3; k4++) {
                float4 bq = *(const float4*)(sBq + 128 * k4 + 4 * lane);
                acc2[rr][2*k4]   = pack2(bq.x, bq.y);
                acc2[rr][2*k4+1] = pack2(bq.z, bq.w);
            }
        }
    }

    for (int d0 = 0; d0 < DMODEL; d0 += 32) {
        for (int t = tid; t < 32 * 384 / 4; t += 256)
            ((float4*)wt)[t] = ((const float4*)(W_qkv + (size_t)d0 * 384))[t];
        __syncthreads();
        #pragma unroll 2
        for (int dk = 0; dk < 16; dk++) {
            ull e2[7];
            #pragma unroll
            for (int rr = 0; rr < 7; rr++) {
                int row = w + 8 * rr;
                if (rr < 6 || wzero)
                    e2[rr] = *(const ull*)(sE + row * DMODEL + d0 + 2 * dk);  // broadcast
            }
            #pragma unroll
            for (int t = 0; t < 2; t++) {
                int dd = 2 * dk + t;
                ulonglong2 wv0 = ((const ulonglong2*)(wt + dd * 384))[lane];
                ulonglong2 wv1 = ((const ulonglong2*)(wt + dd * 384 + 128))[lane];
                ulonglong2 wv2 = ((const ulonglong2*)(wt + dd * 384 + 256))[lane];
                #pragma unroll
                for (int rr = 0; rr < 7; rr++) {
                    if (rr < 6 || wzero) {
                        float elo, ehi;
                        unpack2(e2[rr], elo, ehi);
                        ull ee = dup2(t ? ehi : elo);
                        acc2[rr][0] = fma2(ee, wv0.x, acc2[rr][0]);
                        acc2[rr][1] = fma2(ee, wv0.y, acc2[rr][1]);
                        acc2[rr][2] = fma2(ee, wv1.x, acc2[rr][2]);
                        acc2[rr][3] = fma2(ee, wv1.y, acc2[rr][3]);
                        acc2[rr][4] = fma2(ee, wv2.x, acc2[rr][4]);
                        acc2[rr][5] = fma2(ee, wv2.y, acc2[rr][5]);
                    }
                }
            }
        }
        __syncthreads();
    }

    // ---- zero KT pad cols, scatter q / k^T / v ----
    for (int t = tid; t < 128 * 3; t += 256) {
        int d = t / 3, jz = 49 + (t % 3);
        sKT[d * KTSTR + jz] = 0.f;
    }
    #pragma unroll
    for (int rr = 0; rr < 7; rr++) {
        int row = w + 8 * rr;
        if (rr < 6 || wzero) {
            float q0,q1,q2,q3, k0,k1,k2,k3, v0,v1,v2,v3;
            unpack2(acc2[rr][0], q0, q1); unpack2(acc2[rr][1], q2, q3);
            unpack2(acc2[rr][2], k0, k1); unpack2(acc2[rr][3], k2, k3);
            unpack2(acc2[rr][4], v0, v1); unpack2(acc2[rr][5], v2, v3);
            ((float4*)(sQ + row * DMODEL))[lane] = make_float4(q0, q1, q2, q3);
            ((float4*)(sV + row * DMODEL))[lane] = make_float4(v0, v1, v2, v3);
            int kd = 4 * lane;
            sKT[kd * KTSTR + row] = k0;
            sKT[(kd + 1) * KTSTR + row] = k1;
            sKT[(kd + 2) * KTSTR + row] = k2;
            sKT[(kd + 3) * KTSTR + row] = k3;
        }
    }
    __syncthreads();

    // ================= attention: blk = (head h, 7 i-rows) =================
    const float scale = 0.1767766952966369f;
    float b2v = b2[0];
    ull w1p[16];
    #pragma unroll
    for (int k = 0; k < 16; k++)
        w1p[k] = pack2(sW1[(2 * k) * HD + lane], sW1[(2 * k + 1) * HD + lane]);
    float b1r = sb1[lane], w2r = sW2[lane];
    float m0 = sM[2 * lane], m1 = sM[2 * lane + 1];
    bool vj0 = (2 * lane) < NP1;
    bool vj1 = (2 * lane + 1) < NP1;
    float* spw_base = sP + w * 7 * KTSTR;
    float* sa2w = sA2 + w * 32;

    for (int blk = w; blk < 28; blk += 8) {
        int h = blk & 3;
        int ibase = (blk >> 2) * 7;
        // ---- scores (q via float4 broadcasts) ----
        ull s2[7];
        #pragma unroll
        for (int r = 0; r < 7; r++) s2[r] = 0ull;
        const float* ktb = sKT + (h * HD) * KTSTR + 2 * lane;
        #pragma unroll 2
        for (int dq = 0; dq < 8; dq++) {
            float4 q4[7];
            #pragma unroll
            for (int r = 0; r < 7; r++)
                q4[r] = *(const float4*)(sQ + (ibase + r) * DMODEL + h * HD + 4 * dq);
            #pragma unroll
            for (int t = 0; t < 4; t++) {
                int d = 4 * dq + t;
                ull kv2 = (lane < 26) ? *(const ull*)(ktb + d * KTSTR) : 0ull;
                #pragma unroll
                for (int r = 0; r < 7; r++) {
                    ull qd = dup2(((const float*)&q4[r])[t]);
                    s2[r] = fma2(qd, kv2, s2[r]);
                }
            }
        }
        // ---- softmax -> probs to smem ----
        #pragma unroll
        for (int r = 0; r < 7; r++) {
            float mi = sM[ibase + r];
            float s0, s1;
            unpack2(s2[r], s0, s1);
            float pm0 = mi * m0, pm1 = mi * m1;
            s0 = vj0 ? ((pm0 > 0.f) ? s0 * scale : -1e9f) : -INFINITY;
            s1 = vj1 ? ((pm1 > 0.f) ? s1 * scale : -1e9f) : -INFINITY;
            float mx = warp_max(fmaxf(s0, s1));
            float e0 = vj0 ? expf(s0 - mx) : 0.f;
            float e1 = vj1 ? expf(s1 - mx) : 0.f;
            float inv = 1.0f / warp_sum(e0 + e1);
            if (lane < 26)
                ((ull*)(spw_base + r * KTSTR))[lane] = pack2(e0 * inv, e1 * inv);
        }
        __syncwarp();
        // ---- A2 = probs @ V (probs via float4 broadcast, V rows 1wf each) ----
        ull a2acc[7];
        #pragma unroll
        for (int r = 0; r < 7; r++) a2acc[r] = 0ull;
        const float* vb = sV + h * HD + lane;
        #pragma unroll 3
        for (int jc = 0; jc < 12; jc++) {
            int j0 = 4 * jc;
            ull v01 = pack2(vb[j0 * DMODEL], vb[(j0 + 1) * DMODEL]);
            ull v23 = pack2(vb[(j0 + 2) * DMODEL], vb[(j0 + 3) * DMODEL]);
            #pragma unroll
            for (int r = 0; r < 7; r++) {
                float4 p4 = *(const float4*)(spw_base + r * KTSTR + j0);
                a2acc[r] = fma2(pack2(p4.x, p4.y), v01, a2acc[r]);
                a2acc[r] = fma2(pack2(p4.z, p4.w), v23, a2acc[r]);
            }
        }
        {   // tail j = 48..51 (probs are zero for j>=49; v guarded to stay finite)
            ull v01 = pack2(vb[48 * DMODEL], 0.f);
            #pragma unroll
            for (int r = 0; r < 7; r++) {
                float4 p4 = *(const float4*)(spw_base + r * KTSTR + 48);
                a2acc[r] = fma2(pack2(p4.x, p4.y), v01, a2acc[r]);
            }
        }
        // ---- gating MLP per row ----
        #pragma unroll
        for (int r = 0; r < 7; r++) {
            float alo, ahi;
            unpack2(a2acc[r], alo, ahi);
            sa2w[lane] = alo + ahi;
            __syncwarp();
            ull t2 = pack2(b1r, 0.f);
            #pragma unroll
            for (int cc = 0; cc < 8; cc++) {
                float4 a4 = *(const float4*)(sa2w + 4 * cc);
                t2 = fma2(pack2(a4.x, a4.y), w1p[2 * cc], t2);
                t2 = fma2(pack2(a4.z, a4.w), w1p[2 * cc + 1], t2);
            }
            float tlo, thi;
            unpack2(t2, tlo, thi);
            float t = fmaxf(tlo + thi, 0.f);
            float gp = warp_sum(t * w2r);
            if (lane == 0) sG[h * NP1 + ibase + r] = gp + b2v;
            __syncwarp();
        }
    }
    __syncthreads();

    // ================= em softmax + gumbel (warp = head) =================
    if (w < NHEAD) {
        int h = w;
        int i0 = lane, i1 = lane + 32;
        bool has1 = (i1 < NP1);
        float g0 = sG[h * NP1 + i0];
        float g1 = has1 ? sG[h * NP1 + i1] : -INFINITY;
        float mx = warp_max(fmaxf(g0, g1));
        float e0 = expf(g0 - mx);
        float e1 = has1 ? expf(g1 - mx) : 0.f;
        float inv = 1.0f / warp_sum(e0 + e1);
        float em0 = e0 * inv * sM[i0];
        float em1 = has1 ? e1 * inv * sM[i1] : 0.f;
        float den = warp_sum(em0 + em1) + 1e-10f;
        em0 /= den;
        em1 /= den;
        size_t base = (((size_t)b * NN + j) * NHEAD + h) * NP1;
        out[base + i0] = em0;
        if (has1) out[base + i1] = em1;
        float l0 = logf(em0 + 1e-10f) + gumbel_noise((unsigned)(base + i0));
        float l1 = has1 ? (logf(em1 + 1e-10f) + gumbel_noise((unsigned)(base + i1))) : -INFINITY;
        float mx2 = warp_max(fmaxf(l0, l1));
        float t0 = expf(l0 - mx2);
        float t1 = has1 ? expf(l1 - mx2) : 0.f;
        float inv2 = 1.0f / warp_sum(t0 + t1);
        out[TOTALE + base + i0] = t0 * inv2;
        if (has1) out[TOTALE + base + i1] = t1 * inv2;
    }
}

// ---------------- launch ----------------
extern "C" void kernel_launch(void* const* d_in, const int* in_sizes, int n_in,
                              void* d_out, int out_size) {
    const float* x        = (const float*)d_in[0];
    const float* A        = (const float*)d_in[1];
    const float* amask    = (const float*)d_in[2];
    const float* W_embed  = (const float*)d_in[3];
    const float* b_embed  = (const float*)d_in[4];
    const float* ln_g     = (const float*)d_in[5];
    const float* ln_b     = (const float*)d_in[6];
    const float* W_qkv    = (const float*)d_in[7];
    const float* b_qkv    = (const float*)d_in[8];
    const float* W1       = (const float*)d_in[9];
    const float* b1       = (const float*)d_in[10];
    const float* W2       = (const float*)d_in[11];
    const float* b2       = (const float*)d_in[12];
    float* out = (float*)d_out;

    cudaFuncSetAttribute(k3_attn, cudaFuncAttributeMaxDynamicSharedMemorySize, SMEM3_BYTES);

    k1_pq<<<BSZ * NP1, 128>>>(x, amask, W_embed, b_embed);
    k3_attn<<<BSZ * NN, 256, SMEM3_BYTES>>>(A, amask, W_embed, ln_g, ln_b,
                                            W_qkv, b_qkv, W1, b1, W2, b2, out);
}

// round 6
// speedup vs baseline: 1.7547x; 1.0156x over previous
#include <cuda_runtime.h>

#define BSZ 128
#define NN 48
#define NP1 49
#define DM 32
#define DMODEL 128
#define NHEAD 4
#define HD 32
#define TOTALE (BSZ*NN*NHEAD*NP1)   /* 1204224 */

typedef unsigned long long ull;

// ---------------- device scratch ----------------
__device__ float g_P[BSZ * NP1 * DMODEL];
__device__ float g_Q[BSZ * NN * DMODEL];
__device__ float g_W[DMODEL * 384];   // folded qkv weights
__device__ float g_B[384];            // folded qkv bias

// ---------------- helpers ----------------
__device__ __forceinline__ float warp_sum(float v) {
    #pragma unroll
    for (int o = 16; o > 0; o >>= 1) v += __shfl_xor_sync(0xffffffffu, v, o);
    return v;
}
__device__ __forceinline__ float warp_max(float v) {
    #pragma unroll
    for (int o = 16; o > 0; o >>= 1) v = fmaxf(v, __shfl_xor_sync(0xffffffffu, v, o));
    return v;
}
__device__ __forceinline__ unsigned rotl32(unsigned v, int r) {
    return (v << r) | (v >> (32 - r));
}
__device__ __forceinline__ ull fma2(ull a, ull b, ull c) {
    ull d;
    asm("fma.rn.f32x2 %0, %1, %2, %3;" : "=l"(d) : "l"(a), "l"(b), "l"(c));
    return d;
}
__device__ __forceinline__ ull pack2(float lo, float hi) {
    ull d;
    asm("mov.b64 %0, {%1, %2};" : "=l"(d) : "f"(lo), "f"(hi));
    return d;
}
__device__ __forceinline__ ull dup2(float v) {
    ull d;
    asm("mov.b64 %0, {%1, %1};" : "=l"(d) : "f"(v));
    return d;
}
__device__ __forceinline__ void unpack2(ull v, float& lo, float& hi) {
    asm("mov.b64 {%0, %1}, %2;" : "=f"(lo), "=f"(hi) : "l"(v));
}

// JAX partitionable-threefry gumbel noise (verified R2-R5)
__device__ float gumbel_noise(unsigned idx) {
    unsigned x0 = 0u, x1 = idx;
    const unsigned ks0 = 0u, ks1 = 42u, ks2 = 0x1BD11BDAu ^ 0u ^ 42u;
    x0 += ks0; x1 += ks1;
#define TFR(r) { x0 += x1; x1 = rotl32(x1, r); x1 ^= x0; }
    TFR(13) TFR(15) TFR(26) TFR(6)   x0 += ks1; x1 += ks2 + 1u;
    TFR(17) TFR(29) TFR(16) TFR(24)  x0 += ks2; x1 += ks0 + 2u;
    TFR(13) TFR(15) TFR(26) TFR(6)   x0 += ks0; x1 += ks1 + 3u;
    TFR(17) TFR(29) TFR(16) TFR(24)  x0 += ks1; x1 += ks2 + 4u;
    TFR(13) TFR(15) TFR(26) TFR(6)   x0 += ks2; x1 += ks0 + 5u;
#undef TFR
    unsigned bits = x0 ^ x1;
    float u = __uint_as_float((bits >> 9) | 0x3f800000u) - 1.0f;
    float ex = -log1pf(-u);
    return -logf(ex);
}

// ---------------- kernel 0: fold W1/b1 and q-scale into qkv weights ----------------
// g_W[:,0:128]   = Wq * 32^-0.5        g_B[0:128]   = bq * 32^-0.5
// g_W[:,128:256] = Wk                  g_B[128:256] = bk
// g_W[:,256+32h+d'] = sum_c Wv[:,32h+c] * W1[c][d']
// g_B[256+32h+d'] = sum_c bv[32h+c] * W1[c][d'] + b1[d']
__global__ void k0_fold(const float* __restrict__ W_qkv,
                        const float* __restrict__ b_qkv,
                        const float* __restrict__ W1,
                        const float* __restrict__ b1) {
    int idx = blockIdx.x * 256 + threadIdx.x;
    if (idx >= 129 * 384) return;
    int row = idx / 384, col = idx % 384;
    const float scale = 0.1767766952966369f;  // 32^-0.5
    float val;
    if (col < 256) {
        float s = (row < 128) ? W_qkv[row * 384 + col] : b_qkv[col];
        val = (col < 128) ? s * scale : s;
    } else {
        int h = (col - 256) >> 5, dp = (col - 256) & 31;
        float acc = (row < 128) ? 0.f : b1[dp];
        #pragma unroll 8
        for (int c = 0; c < 32; c++) {
            float s = (row < 128) ? W_qkv[row * 384 + 256 + 32 * h + c]
                                  : b_qkv[256 + 32 * h + c];
            acc = fmaf(s, W1[c * 32 + dp], acc);
        }
        val = acc;
    }
    if (row < 128) g_W[row * 384 + col] = val;
    else g_B[col] = val;
}

// ---------------- kernel 1 ----------------
__global__ void k1_pq(const float* __restrict__ x,
                      const float* __restrict__ attn_mask,
                      const float* __restrict__ W_embed,
                      const float* __restrict__ b_embed) {
    int b = blockIdx.x / NP1;
    int n = blockIdx.x % NP1;
    int d = threadIdx.x;
    if (n == NN) {
        g_P[((size_t)b * NP1 + NN) * DMODEL + d] = b_embed[d];
        return;
    }
    __shared__ float am[NN];
    __shared__ float xm[DM];
    if (d < NN) am[d] = attn_mask[((size_t)b * NN + n) * NN + d];
    __syncthreads();
    float s = 0.f;
    #pragma unroll
    for (int c = 0; c < NN; c++) s += am[c];
    float ped = (s > 0.f) ? 1.f : 0.f;
    if (d < DM) xm[d] = x[((size_t)b * NN + n) * DM + d] * ped;
    __syncthreads();
    float p = b_embed[d];
    float q = 0.f;
    #pragma unroll
    for (int c = 0; c < DM; c++) {
        float xc = xm[c];
        p = fmaf(xc, W_embed[c * DMODEL + d], p);
        q = fmaf(xc, W_embed[(DM + c) * DMODEL + d], q);
    }
    g_P[((size_t)b * NP1 + n) * DMODEL + d] = p;
    g_Q[((size_t)b * NN + n) * DMODEL + d] = q;
}

// ---------------- fused kernel smem layout (floats) ----------------
#define OFF_E   0          /* phase A/B: 49*128 = 6272 */
#define OFF_WA  6272       /* phase A: W_embed rows 64..95, 4096 */
#define OFF_AE  10368      /* phase A: a-staging 56*32 = 1792 (inside WT region) */
#define OFF_WT  6272       /* phase B: W tile 32*384 = 12288 -> ends 18560 */
#define OFF_Q   0          /* phase C: 6272 */
#define OFF_V   6272       /* phase C: V' = V@W1, 6272 */
#define KTSTR   52
#define OFF_KT  12544      /* phase C: 128*52 = 6656 -> ends 19200 */
#define PER     19200
#define OFF_M   (PER+0)    /* 64 */
#define OFF_BQ  (PER+64)   /* 384 */
#define OFF_W2  (PER+448)  /* 32 */
#define OFF_G   (PER+480)  /* 200 */
#define OFF_LG  (PER+680)  /* 128 */
#define OFF_LB  (PER+808)  /* 128 */
#define SMEM3_FLOATS (PER+936)
#define SMEM3_BYTES (SMEM3_FLOATS * 4)

__global__ void __launch_bounds__(256, 2) k3_attn(
    const float* __restrict__ A,
    const float* __restrict__ attn_mask,
    const float* __restrict__ W_embed,
    const float* __restrict__ ln_g,
    const float* __restrict__ ln_b,
    const float* __restrict__ W2,
    const float* __restrict__ b2,
    float* __restrict__ out) {
    extern __shared__ float sm[];
    int bj = blockIdx.x;
    int b = bj / NN, j = bj % NN;
    int tid = threadIdx.x, lane = tid & 31, w = tid >> 5;
    bool wzero = (w == 0);

    float* sE  = sm + OFF_E;
    float* sWA = sm + OFF_WA;
    float* sAE = sm + OFF_AE;
    float* wt  = sm + OFF_WT;
    float* sQ  = sm + OFF_Q;
    float* sV  = sm + OFF_V;
    float* sKT = sm + OFF_KT;
    float* sM  = sm + OFF_M;
    float* sBq = sm + OFF_BQ;
    float* sW2 = sm + OFF_W2;
    float* sG  = sm + OFF_G;
    float* sLG = sm + OFF_LG;
    float* sLB = sm + OFF_LB;

    // ---- persistent loads ----
    if (tid < 64) sM[tid] = (tid < NN) ? attn_mask[((size_t)b * NN + j) * NN + tid]
                                       : (tid == NN ? 1.0f : 0.0f);
    for (int t = tid; t < 384; t += 256) sBq[t] = g_B[t];
    if (tid < 32) sW2[tid] = W2[tid];
    if (tid >= 64 && tid < 192) { sLG[tid - 64] = ln_g[tid - 64]; sLB[tid - 64] = ln_b[tid - 64]; }
    for (int t = tid; t < DM * DMODEL; t += 256) sWA[t] = W_embed[(2 * DM) * DMODEL + t];
    __syncthreads();

    // ================= E + LayerNorm (row-batched per warp) =================
    {
        #pragma unroll
        for (int rr = 0; rr < 7; rr++) {
            int row = w + 8 * rr;
            if (rr < 6 || wzero) {
                float a = 0.f;
                if (row < NN)
                    a = A[(((size_t)b * NN + row) * NN + j) * DM + lane] * sM[row];
                sAE[(w * 7 + rr) * DM + lane] = a;
            }
        }
        __syncwarp();

        const float2* Pb2 = (const float2*)(g_P + (size_t)b * NP1 * DMODEL);
        const float2* Qb2 = (const float2*)(g_Q + ((size_t)b * NN + j) * DMODEL);
        const ull* wt2 = (const ull*)sWA;
        float2 qva = Qb2[lane];
        float2 qvb = Qb2[32 + lane];
        float lg0 = sLG[2*lane], lg1 = sLG[2*lane+1], lg2 = sLG[64+2*lane], lg3 = sLG[64+2*lane+1];
        float lb0 = sLB[2*lane], lb1 = sLB[2*lane+1], lb2 = sLB[64+2*lane], lb3 = sLB[64+2*lane+1];

        ull e0[7], e1[7];
        #pragma unroll
        for (int rr = 0; rr < 7; rr++) {
            int row = w + 8 * rr;
            if (rr < 6 || wzero) {
                float2 p0 = Pb2[row * 64 + lane];
                float2 p1 = Pb2[row * 64 + 32 + lane];
                e0[rr] = pack2(p0.x + qva.x, p0.y + qva.y);
                e1[rr] = pack2(p1.x + qvb.x, p1.y + qvb.y);
            }
        }
        #pragma unroll 2
        for (int cg = 0; cg < 8; cg++) {
            float4 a4[7];
            #pragma unroll
            for (int rr = 0; rr < 7; rr++)
                if (rr < 6 || wzero)
                    a4[rr] = *(const float4*)(sAE + (w * 7 + rr) * DM + 4 * cg);
            #pragma unroll
            for (int t = 0; t < 4; t++) {
                int c = 4 * cg + t;
                ull wv0 = wt2[c * 64 + lane];
                ull wv1 = wt2[c * 64 + 32 + lane];
                #pragma unroll
                for (int rr = 0; rr < 7; rr++) {
                    if (rr < 6 || wzero) {
                        ull ac = dup2(((const float*)&a4[rr])[t]);
                        e0[rr] = fma2(ac, wv0, e0[rr]);
                        e1[rr] = fma2(ac, wv1, e1[rr]);
                    }
                }
            }
        }
        #pragma unroll
        for (int rr = 0; rr < 7; rr++) {
            int row = w + 8 * rr;
            if (rr < 6 || wzero) {
                float v0, v1, v2, v3;
                unpack2(e0[rr], v0, v1); unpack2(e1[rr], v2, v3);
                float mu = warp_sum(v0 + v1 + v2 + v3) * (1.0f / DMODEL);
                float d0 = v0 - mu, d1 = v1 - mu, d2 = v2 - mu, d3 = v3 - mu;
                float rs = rsqrtf(warp_sum(d0*d0 + d1*d1 + d2*d2 + d3*d3) * (1.0f / DMODEL) + 1e-5f);
                float2* dst = (float2*)(sE + row * DMODEL);
                dst[lane]      = make_float2(d0 * rs * lg0 + lb0, d1 * rs * lg1 + lb1);
                dst[32 + lane] = make_float2(d2 * rs * lg2 + lb2, d3 * rs * lg3 + lb3);
            }
        }
    }
    __syncthreads();

    // ================= qkv GEMM (folded weights g_W) =================
    ull acc2[7][6];
    #pragma unroll
    for (int rr = 0; rr < 7; rr++) {
        if (rr < 6 || wzero) {
            #pragma unroll
            for (int k4 = 0; k4 < 3; k4++) {
                float4 bq = *(const float4*)(sBq + 128 * k4 + 4 * lane);
                acc2[rr][2*k4]   = pack2(bq.x, bq.y);
                acc2[rr][2*k4+1] = pack2(bq.z, bq.w);
            }
        }
    }

    for (int d0 = 0; d0 < DMODEL; d0 += 32) {
        for (int t = tid; t < 32 * 384 / 4; t += 256)
            ((float4*)wt)[t] = ((const float4*)(g_W + (size_t)d0 * 384))[t];
        __syncthreads();
        #pragma unroll 2
        for (int dk = 0; dk < 16; dk++) {
            ull e2[7];
            #pragma unroll
            for (int rr = 0; rr < 7; rr++) {
                int row = w + 8 * rr;
                if (rr < 6 || wzero)
                    e2[rr] = *(const ull*)(sE + row * DMODEL + d0 + 2 * dk);  // broadcast
            }
            #pragma unroll
            for (int t = 0; t < 2; t++) {
                int dd = 2 * dk + t;
                ulonglong2 wv0 = ((const ulonglong2*)(wt + dd * 384))[lane];
                ulonglong2 wv1 = ((const ulonglong2*)(wt + dd * 384 + 128))[lane];
                ulonglong2 wv2 = ((const ulonglong2*)(wt + dd * 384 + 256))[lane];
                #pragma unroll
                for (int rr = 0; rr < 7; rr++) {
                    if (rr < 6 || wzero) {
                        float elo, ehi;
                        unpack2(e2[rr], elo, ehi);
                        ull ee = dup2(t ? ehi : elo);
                        acc2[rr][0] = fma2(ee, wv0.x, acc2[rr][0]);
                        acc2[rr][1] = fma2(ee, wv0.y, acc2[rr][1]);
                        acc2[rr][2] = fma2(ee, wv1.x, acc2[rr][2]);
                        acc2[rr][3] = fma2(ee, wv1.y, acc2[rr][3]);
                        acc2[rr][4] = fma2(ee, wv2.x, acc2[rr][4]);
                        acc2[rr][5] = fma2(ee, wv2.y, acc2[rr][5]);
                    }
                }
            }
        }
        __syncthreads();
    }

    // ---- zero KT pad cols, scatter q / k^T / v' ----
    for (int t = tid; t < 128 * 3; t += 256) {
        int d = t / 3, jz = 49 + (t % 3);
        sKT[d * KTSTR + jz] = 0.f;
    }
    #pragma unroll
    for (int rr = 0; rr < 7; rr++) {
        int row = w + 8 * rr;
        if (rr < 6 || wzero) {
            float q0,q1,q2,q3, k0,k1,k2,k3, v0,v1,v2,v3;
            unpack2(acc2[rr][0], q0, q1); unpack2(acc2[rr][1], q2, q3);
            unpack2(acc2[rr][2], k0, k1); unpack2(acc2[rr][3], k2, k3);
            unpack2(acc2[rr][4], v0, v1); unpack2(acc2[rr][5], v2, v3);
            ((float4*)(sQ + row * DMODEL))[lane] = make_float4(q0, q1, q2, q3);
            ((float4*)(sV + row * DMODEL))[lane] = make_float4(v0, v1, v2, v3);
            int kd = 4 * lane;
            sKT[kd * KTSTR + row] = k0;
            sKT[(kd + 1) * KTSTR + row] = k1;
            sKT[(kd + 2) * KTSTR + row] = k2;
            sKT[(kd + 3) * KTSTR + row] = k3;
        }
    }
    __syncthreads();

    // ================= attention: blk = (head h, 7 i-rows) =================
    float b2v = b2[0];
    float w2r = sW2[lane];
    float m0 = sM[2 * lane], m1 = sM[2 * lane + 1];
    bool vj0 = (2 * lane) < NP1;
    bool vj1 = (2 * lane + 1) < NP1;

    for (int blk = w; blk < 28; blk += 8) {
        int h = blk & 3;
        int ibase = (blk >> 2) * 7;
        // ---- scores (q pre-scaled via folded weights) ----
        ull s2[7];
        #pragma unroll
        for (int r = 0; r < 7; r++) s2[r] = 0ull;
        const float* ktb = sKT + (h * HD) * KTSTR + 2 * lane;
        #pragma unroll 2
        for (int dq = 0; dq < 8; dq++) {
            float4 q4[7];
            #pragma unroll
            for (int r = 0; r < 7; r++)
                q4[r] = *(const float4*)(sQ + (ibase + r) * DMODEL + h * HD + 4 * dq);
            #pragma unroll
            for (int t = 0; t < 4; t++) {
                int d = 4 * dq + t;
                ull kv2 = (lane < 26) ? *(const ull*)(ktb + d * KTSTR) : 0ull;
                #pragma unroll
                for (int r = 0; r < 7; r++) {
                    ull qd = dup2(((const float*)&q4[r])[t]);
                    s2[r] = fma2(qd, kv2, s2[r]);
                }
            }
        }
        // ---- masked softmax, UNNORMALIZED probs in registers + inv ----
        ull p2[7];
        float invr[7];
        #pragma unroll
        for (int r = 0; r < 7; r++) {
            float mi = sM[ibase + r];
            float s0, s1;
            unpack2(s2[r], s0, s1);
            float pm0 = mi * m0, pm1 = mi * m1;
            s0 = vj0 ? ((pm0 > 0.f) ? s0 : -1e9f) : -INFINITY;
            s1 = vj1 ? ((pm1 > 0.f) ? s1 : -1e9f) : -INFINITY;
            float mx = warp_max(fmaxf(s0, s1));
            float e0 = vj0 ? expf(s0 - mx) : 0.f;
            float e1 = vj1 ? expf(s1 - mx) : 0.f;
            invr[r] = 1.0f / warp_sum(e0 + e1);
            p2[r] = pack2(e0, e1);
        }
        // ---- gate-pre = probs @ V' (V' = V@W1 + folded bias; lane = d) ----
        ull t2[7];
        #pragma unroll
        for (int r = 0; r < 7; r++) t2[r] = 0ull;
        const float* vb = sV + h * HD + lane;
        #pragma unroll 5
        for (int jp = 0; jp < 25; jp++) {
            // jp=24 hi element reads sKT start (finite) x prob 0 -> harmless
            ull v2 = pack2(vb[(2 * jp) * DMODEL], vb[(2 * jp + 1) * DMODEL]);
            #pragma unroll
            for (int r = 0; r < 7; r++) {
                ull pp = __shfl_sync(0xffffffffu, p2[r], jp);
                t2[r] = fma2(pp, v2, t2[r]);
            }
        }
        // ---- gate = relu(inv * tpre) . W2 + b2 ----
        #pragma unroll
        for (int r = 0; r < 7; r++) {
            float tlo, thi;
            unpack2(t2[r], tlo, thi);
            float t = fmaxf((tlo + thi) * invr[r], 0.f);
            float gp = warp_sum(t * w2r);
            if (lane == 0) sG[h * NP1 + ibase + r] = gp + b2v;
        }
    }
    __syncthreads();

    // ================= em softmax + gumbel (warp = head) =================
    if (w < NHEAD) {
        int h = w;
        int i0 = lane, i1 = lane + 32;
        bool has1 = (i1 < NP1);
        float g0 = sG[h * NP1 + i0];
        float g1 = has1 ? sG[h * NP1 + i1] : -INFINITY;
        float mx = warp_max(fmaxf(g0, g1));
        float e0 = expf(g0 - mx);
        float e1 = has1 ? expf(g1 - mx) : 0.f;
        float inv = 1.0f / warp_sum(e0 + e1);
        float em0 = e0 * inv * sM[i0];
        float em1 = has1 ? e1 * inv * sM[i1] : 0.f;
        float den = warp_sum(em0 + em1) + 1e-10f;
        em0 /= den;
        em1 /= den;
        size_t base = (((size_t)b * NN + j) * NHEAD + h) * NP1;
        out[base + i0] = em0;
        if (has1) out[base + i1] = em1;
        float l0 = logf(em0 + 1e-10f) + gumbel_noise((unsigned)(base + i0));
        float l1 = has1 ? (logf(em1 + 1e-10f) + gumbel_noise((unsigned)(base + i1))) : -INFINITY;
        float mx2 = warp_max(fmaxf(l0, l1));
        float t0 = expf(l0 - mx2);
        float t1 = has1 ? expf(l1 - mx2) : 0.f;
        float inv2 = 1.0f / warp_sum(t0 + t1);
        out[TOTALE + base + i0] = t0 * inv2;
        if (has1) out[TOTALE + base + i1] = t1 * inv2;
    }
}

// ---------------- launch ----------------
extern "C" void kernel_launch(void* const* d_in, const int* in_sizes, int n_in,
                              void* d_out, int out_size) {
    const float* x        = (const float*)d_in[0];
    const float* A        = (const float*)d_in[1];
    const float* amask    = (const float*)d_in[2];
    const float* W_embed  = (const float*)d_in[3];
    const float* b_embed  = (const float*)d_in[4];
    const float* ln_g     = (const float*)d_in[5];
    const float* ln_b     = (const float*)d_in[6];
    const float* W_qkv    = (const float*)d_in[7];
    const float* b_qkv    = (const float*)d_in[8];
    const float* W1       = (const float*)d_in[9];
    const float* b1       = (const float*)d_in[10];
    const float* W2       = (const float*)d_in[11];
    const float* b2       = (const float*)d_in[12];
    float* out = (float*)d_out;

    cudaFuncSetAttribute(k3_attn, cudaFuncAttributeMaxDynamicSharedMemorySize, SMEM3_BYTES);

    k0_fold<<<(129 * 384 + 255) / 256, 256>>>(W_qkv, b_qkv, W1, b1);
    k1_pq<<<BSZ * NP1, 128>>>(x, amask, W_embed, b_embed);
    k3_attn<<<BSZ * NN, 256, SMEM3_BYTES>>>(A, amask, W_embed, ln_g, ln_b,
                                            W2, b2, out);
}

// round 7
// speedup vs baseline: 1.7569x; 1.0013x over previous
#include <cuda_runtime.h>

#define BSZ 128
#define NN 48
#define NP1 49
#define DM 32
#define DMODEL 128
#define NHEAD 4
#define HD 32
#define TOTALE (BSZ*NN*NHEAD*NP1)   /* 1204224 */

typedef unsigned long long ull;

// ---------------- device scratch ----------------
__device__ float g_P[BSZ * NP1 * DMODEL];
__device__ float g_Q[BSZ * NN * DMODEL];
__device__ float g_W[DMODEL * 384];   // folded qkv weights
__device__ float g_B[384];            // folded qkv bias

// ---------------- helpers ----------------
__device__ __forceinline__ float warp_sum(float v) {
    #pragma unroll
    for (int o = 16; o > 0; o >>= 1) v += __shfl_xor_sync(0xffffffffu, v, o);
    return v;
}
__device__ __forceinline__ float warp_max(float v) {
    #pragma unroll
    for (int o = 16; o > 0; o >>= 1) v = fmaxf(v, __shfl_xor_sync(0xffffffffu, v, o));
    return v;
}
__device__ __forceinline__ unsigned rotl32(unsigned v, int r) {
    return (v << r) | (v >> (32 - r));
}
__device__ __forceinline__ ull fma2(ull a, ull b, ull c) {
    ull d;
    asm("fma.rn.f32x2 %0, %1, %2, %3;" : "=l"(d) : "l"(a), "l"(b), "l"(c));
    return d;
}
__device__ __forceinline__ ull pack2(float lo, float hi) {
    ull d;
    asm("mov.b64 %0, {%1, %2};" : "=l"(d) : "f"(lo), "f"(hi));
    return d;
}
__device__ __forceinline__ ull dup2(float v) {
    ull d;
    asm("mov.b64 %0, {%1, %1};" : "=l"(d) : "f"(v));
    return d;
}
__device__ __forceinline__ void unpack2(ull v, float& lo, float& hi) {
    asm("mov.b64 {%0, %1}, %2;" : "=f"(lo), "=f"(hi) : "l"(v));
}

// JAX partitionable-threefry gumbel noise (verified R2-R5)
__device__ float gumbel_noise(unsigned idx) {
    unsigned x0 = 0u, x1 = idx;
    const unsigned ks0 = 0u, ks1 = 42u, ks2 = 0x1BD11BDAu ^ 0u ^ 42u;
    x0 += ks0; x1 += ks1;
#define TFR(r) { x0 += x1; x1 = rotl32(x1, r); x1 ^= x0; }
    TFR(13) TFR(15) TFR(26) TFR(6)   x0 += ks1; x1 += ks2 + 1u;
    TFR(17) TFR(29) TFR(16) TFR(24)  x0 += ks2; x1 += ks0 + 2u;
    TFR(13) TFR(15) TFR(26) TFR(6)   x0 += ks0; x1 += ks1 + 3u;
    TFR(17) TFR(29) TFR(16) TFR(24)  x0 += ks1; x1 += ks2 + 4u;
    TFR(13) TFR(15) TFR(26) TFR(6)   x0 += ks2; x1 += ks0 + 5u;
#undef TFR
    unsigned bits = x0 ^ x1;
    float u = __uint_as_float((bits >> 9) | 0x3f800000u) - 1.0f;
    float ex = -log1pf(-u);
    return -logf(ex);
}

// ---------------- kernel 0: fold W1/b1 and q-scale into qkv weights ----------------
// g_W[:,0:128]   = Wq * 32^-0.5        g_B[0:128]   = bq * 32^-0.5
// g_W[:,128:256] = Wk                  g_B[128:256] = bk
// g_W[:,256+32h+d'] = sum_c Wv[:,32h+c] * W1[c][d']
// g_B[256+32h+d'] = sum_c bv[32h+c] * W1[c][d'] + b1[d']
__global__ void k0_fold(const float* __restrict__ W_qkv,
                        const float* __restrict__ b_qkv,
                        const float* __restrict__ W1,
                        const float* __restrict__ b1) {
    int idx = blockIdx.x * 256 + threadIdx.x;
    if (idx >= 129 * 384) return;
    int row = idx / 384, col = idx % 384;
    const float scale = 0.1767766952966369f;  // 32^-0.5
    float val;
    if (col < 256) {
        float s = (row < 128) ? W_qkv[row * 384 + col] : b_qkv[col];
        val = (col < 128) ? s * scale : s;
    } else {
        int h = (col - 256) >> 5, dp = (col - 256) & 31;
        float acc = (row < 128) ? 0.f : b1[dp];
        #pragma unroll 8
        for (int c = 0; c < 32; c++) {
            float s = (row < 128) ? W_qkv[row * 384 + 256 + 32 * h + c]
                                  : b_qkv[256 + 32 * h + c];
            acc = fmaf(s, W1[c * 32 + dp], acc);
        }
        val = acc;
    }
    if (row < 128) g_W[row * 384 + col] = val;
    else g_B[col] = val;
}

// ---------------- kernel 1 ----------------
__global__ void k1_pq(const float* __restrict__ x,
                      const float* __restrict__ attn_mask,
                      const float* __restrict__ W_embed,
                      const float* __restrict__ b_embed) {
    int b = blockIdx.x / NP1;
    int n = blockIdx.x % NP1;
    int d = threadIdx.x;
    if (n == NN) {
        g_P[((size_t)b * NP1 + NN) * DMODEL + d] = b_embed[d];
        return;
    }
    __shared__ float am[NN];
    __shared__ float xm[DM];
    if (d < NN) am[d] = attn_mask[((size_t)b * NN + n) * NN + d];
    __syncthreads();
    float s = 0.f;
    #pragma unroll
    for (int c = 0; c < NN; c++) s += am[c];
    float ped = (s > 0.f) ? 1.f : 0.f;
    if (d < DM) xm[d] = x[((size_t)b * NN + n) * DM + d] * ped;
    __syncthreads();
    float p = b_embed[d];
    float q = 0.f;
    #pragma unroll
    for (int c = 0; c < DM; c++) {
        float xc = xm[c];
        p = fmaf(xc, W_embed[c * DMODEL + d], p);
        q = fmaf(xc, W_embed[(DM + c) * DMODEL + d], q);
    }
    g_P[((size_t)b * NP1 + n) * DMODEL + d] = p;
    g_Q[((size_t)b * NN + n) * DMODEL + d] = q;
}

// ---------------- fused kernel smem layout (floats) ----------------
#define OFF_E   0          /* phase A/B: 49*128 = 6272 */
#define OFF_WA  6272       /* phase A: W_embed rows 64..95, 4096 */
#define OFF_AE  10368      /* phase A: a-staging 56*32 = 1792 (inside WT region) */
#define OFF_WT  6272       /* phase B: W tile 32*384 = 12288 -> ends 18560 */
#define OFF_Q   0          /* phase C: 6272 */
#define OFF_V   6272       /* phase C: V' = V@W1, 6272 */
#define KTSTR   52
#define OFF_KT  12544      /* phase C: 128*52 = 6656 -> ends 19200 */
#define PER     19200
#define OFF_M   (PER+0)    /* 64 */
#define OFF_BQ  (PER+64)   /* 384 */
#define OFF_W2  (PER+448)  /* 32 */
#define OFF_G   (PER+480)  /* 200 */
#define OFF_LG  (PER+680)  /* 128 */
#define OFF_LB  (PER+808)  /* 128 */
#define SMEM3_FLOATS (PER+936)
#define SMEM3_BYTES (SMEM3_FLOATS * 4)

__global__ void __launch_bounds__(256, 2) k3_attn(
    const float* __restrict__ A,
    const float* __restrict__ attn_mask,
    const float* __restrict__ W_embed,
    const float* __restrict__ ln_g,
    const float* __restrict__ ln_b,
    const float* __restrict__ W2,
    const float* __restrict__ b2,
    float* __restrict__ out) {
    extern __shared__ float sm[];
    int bj = blockIdx.x;
    int b = bj / NN, j = bj % NN;
    int tid = threadIdx.x, lane = tid & 31, w = tid >> 5;
    bool wzero = (w == 0);

    float* sE  = sm + OFF_E;
    float* sWA = sm + OFF_WA;
    float* sAE = sm + OFF_AE;
    float* wt  = sm + OFF_WT;
    float* sQ  = sm + OFF_Q;
    float* sV  = sm + OFF_V;
    float* sKT = sm + OFF_KT;
    float* sM  = sm + OFF_M;
    float* sBq = sm + OFF_BQ;
    float* sW2 = sm + OFF_W2;
    float* sG  = sm + OFF_G;
    float* sLG = sm + OFF_LG;
    float* sLB = sm + OFF_LB;

    // ---- persistent loads ----
    if (tid < 64) sM[tid] = (tid < NN) ? attn_mask[((size_t)b * NN + j) * NN + tid]
                                       : (tid == NN ? 1.0f : 0.0f);
    for (int t = tid; t < 384; t += 256) sBq[t] = g_B[t];
    if (tid < 32) sW2[tid] = W2[tid];
    if (tid >= 64 && tid < 192) { sLG[tid - 64] = ln_g[tid - 64]; sLB[tid - 64] = ln_b[tid - 64]; }
    for (int t = tid; t < DM * DMODEL; t += 256) sWA[t] = W_embed[(2 * DM) * DMODEL + t];
    __syncthreads();

    // ================= E + LayerNorm (row-batched per warp) =================
    {
        #pragma unroll
        for (int rr = 0; rr < 7; rr++) {
            int row = w + 8 * rr;
            if (rr < 6 || wzero) {
                float a = 0.f;
                if (row < NN)
                    a = A[(((size_t)b * NN + row) * NN + j) * DM + lane] * sM[row];
                sAE[(w * 7 + rr) * DM + lane] = a;
            }
        }
        __syncwarp();

        const float2* Pb2 = (const float2*)(g_P + (size_t)b * NP1 * DMODEL);
        const float2* Qb2 = (const float2*)(g_Q + ((size_t)b * NN + j) * DMODEL);
        const ull* wt2 = (const ull*)sWA;
        float2 qva = Qb2[lane];
        float2 qvb = Qb2[32 + lane];
        float lg0 = sLG[2*lane], lg1 = sLG[2*lane+1], lg2 = sLG[64+2*lane], lg3 = sLG[64+2*lane+1];
        float lb0 = sLB[2*lane], lb1 = sLB[2*lane+1], lb2 = sLB[64+2*lane], lb3 = sLB[64+2*lane+1];

        ull e0[7], e1[7];
        #pragma unroll
        for (int rr = 0; rr < 7; rr++) {
            int row = w + 8 * rr;
            if (rr < 6 || wzero) {
                float2 p0 = Pb2[row * 64 + lane];
                float2 p1 = Pb2[row * 64 + 32 + lane];
                e0[rr] = pack2(p0.x + qva.x, p0.y + qva.y);
                e1[rr] = pack2(p1.x + qvb.x, p1.y + qvb.y);
            }
        }
        #pragma unroll 2
        for (int cg = 0; cg < 8; cg++) {
            float4 a4[7];
            #pragma unroll
            for (int rr = 0; rr < 7; rr++)
                if (rr < 6 || wzero)
                    a4[rr] = *(const float4*)(sAE + (w * 7 + rr) * DM + 4 * cg);
            #pragma unroll
            for (int t = 0; t < 4; t++) {
                int c = 4 * cg + t;
                ull wv0 = wt2[c * 64 + lane];
                ull wv1 = wt2[c * 64 + 32 + lane];
                #pragma unroll
                for (int rr = 0; rr < 7; rr++) {
                    if (rr < 6 || wzero) {
                        ull ac = dup2(((const float*)&a4[rr])[t]);
                        e0[rr] = fma2(ac, wv0, e0[rr]);
                        e1[rr] = fma2(ac, wv1, e1[rr]);
                    }
                }
            }
        }
        #pragma unroll
        for (int rr = 0; rr < 7; rr++) {
            int row = w + 8 * rr;
            if (rr < 6 || wzero) {
                float v0, v1, v2, v3;
                unpack2(e0[rr], v0, v1); unpack2(e1[rr], v2, v3);
                float mu = warp_sum(v0 + v1 + v2 + v3) * (1.0f / DMODEL);
                float d0 = v0 - mu, d1 = v1 - mu, d2 = v2 - mu, d3 = v3 - mu;
                float rs = rsqrtf(warp_sum(d0*d0 + d1*d1 + d2*d2 + d3*d3) * (1.0f / DMODEL) + 1e-5f);
                float2* dst = (float2*)(sE + row * DMODEL);
                dst[lane]      = make_float2(d0 * rs * lg0 + lb0, d1 * rs * lg1 + lb1);
                dst[32 + lane] = make_float2(d2 * rs * lg2 + lb2, d3 * rs * lg3 + lb3);
            }
        }
    }
    __syncthreads();

    // ================= qkv GEMM (folded weights g_W) =================
    ull acc2[7][6];
    #pragma unroll
    for (int rr = 0; rr < 7; rr++) {
        if (rr < 6 || wzero) {
            #pragma unroll
            for (int k4 = 0; k4 < 3; k4++) {
                float4 bq = *(const float4*)(sBq + 128 * k4 + 4 * lane);
                acc2[rr][2*k4]   = pack2(bq.x, bq.y);
                acc2[rr][2*k4+1] = pack2(bq.z, bq.w);
            }
        }
    }

    for (int d0 = 0; d0 < DMODEL; d0 += 32) {
        for (int t = tid; t < 32 * 384 / 4; t += 256)
            ((float4*)wt)[t] = ((const float4*)(g_W + (size_t)d0 * 384))[t];
        __syncthreads();
        #pragma unroll 2
        for (int dk = 0; dk < 16; dk++) {
            ull e2[7];
            #pragma unroll
            for (int rr = 0; rr < 7; rr++) {
                int row = w + 8 * rr;
                if (rr < 6 || wzero)
                    e2[rr] = *(const ull*)(sE + row * DMODEL + d0 + 2 * dk);  // broadcast
            }
            #pragma unroll
            for (int t = 0; t < 2; t++) {
                int dd = 2 * dk + t;
                ulonglong2 wv0 = ((const ulonglong2*)(wt + dd * 384))[lane];
                ulonglong2 wv1 = ((const ulonglong2*)(wt + dd * 384 + 128))[lane];
                ulonglong2 wv2 = ((const ulonglong2*)(wt + dd * 384 + 256))[lane];
                #pragma unroll
                for (int rr = 0; rr < 7; rr++) {
                    if (rr < 6 || wzero) {
                        float elo, ehi;
                        unpack2(e2[rr], elo, ehi);
                        ull ee = dup2(t ? ehi : elo);
                        acc2[rr][0] = fma2(ee, wv0.x, acc2[rr][0]);
                        acc2[rr][1] = fma2(ee, wv0.y, acc2[rr][1]);
                        acc2[rr][2] = fma2(ee, wv1.x, acc2[rr][2]);
                        acc2[rr][3] = fma2(ee, wv1.y, acc2[rr][3]);
                        acc2[rr][4] = fma2(ee, wv2.x, acc2[rr][4]);
                        acc2[rr][5] = fma2(ee, wv2.y, acc2[rr][5]);
                    }
                }
            }
        }
        __syncthreads();
    }

    // ---- zero KT pad cols, scatter q / k^T / v' ----
    for (int t = tid; t < 128 * 3; t += 256) {
        int d = t / 3, jz = 49 + (t % 3);
        sKT[d * KTSTR + jz] = 0.f;
    }
    #pragma unroll
    for (int rr = 0; rr < 7; rr++) {
        int row = w + 8 * rr;
        if (rr < 6 || wzero) {
            float q0,q1,q2,q3, k0,k1,k2,k3, v0,v1,v2,v3;
            unpack2(acc2[rr][0], q0, q1); unpack2(acc2[rr][1], q2, q3);
            unpack2(acc2[rr][2], k0, k1); unpack2(acc2[rr][3], k2, k3);
            unpack2(acc2[rr][4], v0, v1); unpack2(acc2[rr][5], v2, v3);
            ((float4*)(sQ + row * DMODEL))[lane] = make_float4(q0, q1, q2, q3);
            ((float4*)(sV + row * DMODEL))[lane] = make_float4(v0, v1, v2, v3);
            int kd = 4 * lane;
            sKT[kd * KTSTR + row] = k0;
            sKT[(kd + 1) * KTSTR + row] = k1;
            sKT[(kd + 2) * KTSTR + row] = k2;
            sKT[(kd + 3) * KTSTR + row] = k3;
        }
    }
    __syncthreads();

    // ================= attention: blk = (head h, 7 i-rows) =================
    float b2v = b2[0];
    float w2r = sW2[lane];
    float m0 = sM[2 * lane], m1 = sM[2 * lane + 1];
    bool vj0 = (2 * lane) < NP1;
    bool vj1 = (2 * lane + 1) < NP1;

    for (int blk = w; blk < 28; blk += 8) {
        int h = blk & 3;
        int ibase = (blk >> 2) * 7;
        // ---- scores (q pre-scaled via folded weights) ----
        ull s2[7];
        #pragma unroll
        for (int r = 0; r < 7; r++) s2[r] = 0ull;
        const float* ktb = sKT + (h * HD) * KTSTR + 2 * lane;
        #pragma unroll 2
        for (int dq = 0; dq < 8; dq++) {
            float4 q4[7];
            #pragma unroll
            for (int r = 0; r < 7; r++)
                q4[r] = *(const float4*)(sQ + (ibase + r) * DMODEL + h * HD + 4 * dq);
            #pragma unroll
            for (int t = 0; t < 4; t++) {
                int d = 4 * dq + t;
                ull kv2 = (lane < 26) ? *(const ull*)(ktb + d * KTSTR) : 0ull;
                #pragma unroll
                for (int r = 0; r < 7; r++) {
                    ull qd = dup2(((const float*)&q4[r])[t]);
                    s2[r] = fma2(qd, kv2, s2[r]);
                }
            }
        }
        // ---- masked softmax, UNNORMALIZED probs in registers + inv ----
        ull p2[7];
        float invr[7];
        #pragma unroll
        for (int r = 0; r < 7; r++) {
            float mi = sM[ibase + r];
            float s0, s1;
            unpack2(s2[r], s0, s1);
            float pm0 = mi * m0, pm1 = mi * m1;
            s0 = vj0 ? ((pm0 > 0.f) ? s0 : -1e9f) : -INFINITY;
            s1 = vj1 ? ((pm1 > 0.f) ? s1 : -1e9f) : -INFINITY;
            float mx = warp_max(fmaxf(s0, s1));
            float e0 = vj0 ? expf(s0 - mx) : 0.f;
            float e1 = vj1 ? expf(s1 - mx) : 0.f;
            invr[r] = 1.0f / warp_sum(e0 + e1);
            p2[r] = pack2(e0, e1);
        }
        // ---- gate-pre = probs @ V' (V' = V@W1 + folded bias; lane = d) ----
        ull t2[7];
        #pragma unroll
        for (int r = 0; r < 7; r++) t2[r] = 0ull;
        const float* vb = sV + h * HD + lane;
        #pragma unroll 5
        for (int jp = 0; jp < 25; jp++) {
            // jp=24 hi element reads sKT start (finite) x prob 0 -> harmless
            ull v2 = pack2(vb[(2 * jp) * DMODEL], vb[(2 * jp + 1) * DMODEL]);
            #pragma unroll
            for (int r = 0; r < 7; r++) {
                ull pp = __shfl_sync(0xffffffffu, p2[r], jp);
                t2[r] = fma2(pp, v2, t2[r]);
            }
        }
        // ---- gate = relu(inv * tpre) . W2 + b2 ----
        #pragma unroll
        for (int r = 0; r < 7; r++) {
            float tlo, thi;
            unpack2(t2[r], tlo, thi);
            float t = fmaxf((tlo + thi) * invr[r], 0.f);
            float gp = warp_sum(t * w2r);
            if (lane == 0) sG[h * NP1 + ibase + r] = gp + b2v;
        }
    }
    __syncthreads();

    // ================= em softmax + gumbel (warp = head) =================
    if (w < NHEAD) {
        int h = w;
        int i0 = lane, i1 = lane + 32;
        bool has1 = (i1 < NP1);
        float g0 = sG[h * NP1 + i0];
        float g1 = has1 ? sG[h * NP1 + i1] : -INFINITY;
        float mx = warp_max(fmaxf(g0, g1));
        float e0 = expf(g0 - mx);
        float e1 = has1 ? expf(g1 - mx) : 0.f;
        float inv = 1.0f / warp_sum(e0 + e1);
        float em0 = e0 * inv * sM[i0];
        float em1 = has1 ? e1 * inv * sM[i1] : 0.f;
        float den = warp_sum(em0 + em1) + 1e-10f;
        em0 /= den;
        em1 /= den;
        size_t base = (((size_t)b * NN + j) * NHEAD + h) * NP1;
        out[base + i0] = em0;
        if (has1) out[base + i1] = em1;
        float l0 = logf(em0 + 1e-10f) + gumbel_noise((unsigned)(base + i0));
        float l1 = has1 ? (logf(em1 + 1e-10f) + gumbel_noise((unsigned)(base + i1))) : -INFINITY;
        float mx2 = warp_max(fmaxf(l0, l1));
        float t0 = expf(l0 - mx2);
        float t1 = has1 ? expf(l1 - mx2) : 0.f;
        float inv2 = 1.0f / warp_sum(t0 + t1);
        out[TOTALE + base + i0] = t0 * inv2;
        if (has1) out[TOTALE + base + i1] = t1 * inv2;
    }
}

// ---------------- launch ----------------
extern "C" void kernel_launch(void* const* d_in, const int* in_sizes, int n_in,
                              void* d_out, int out_size) {
    const float* x        = (const float*)d_in[0];
    const float* A        = (const float*)d_in[1];
    const float* amask    = (const float*)d_in[2];
    const float* W_embed  = (const float*)d_in[3];
    const float* b_embed  = (const float*)d_in[4];
    const float* ln_g     = (const float*)d_in[5];
    const float* ln_b     = (const float*)d_in[6];
    const float* W_qkv    = (const float*)d_in[7];
    const float* b_qkv    = (const float*)d_in[8];
    const float* W1       = (const float*)d_in[9];
    const float* b1       = (const float*)d_in[10];
    const float* W2       = (const float*)d_in[11];
    const float* b2       = (const float*)d_in[12];
    float* out = (float*)d_out;

    cudaFuncSetAttribute(k3_attn, cudaFuncAttributeMaxDynamicSharedMemorySize, SMEM3_BYTES);

    k0_fold<<<(129 * 384 + 255) / 256, 256>>>(W_qkv, b_qkv, W1, b1);
    k1_pq<<<BSZ * NP1, 128>>>(x, amask, W_embed, b_embed);
    k3_attn<<<BSZ * NN, 256, SMEM3_BYTES>>>(A, amask, W_embed, ln_g, ln_b,
                                            W2, b2, out);
}

// round 10
// speedup vs baseline: 2.4289x; 1.3825x over previous
#include <cuda_runtime.h>
#include <cstdint>

#define BSZ 128
#define NN 48
#define NP1 49
#define DM 32
#define DMODEL 128
#define NHEAD 4
#define HD 32
#define TOTALE (BSZ*NN*NHEAD*NP1)

typedef unsigned long long ull;

// ---------------- device scratch ----------------
__device__ float g_P[BSZ * NP1 * DMODEL];
__device__ float g_Q[BSZ * NN * DMODEL];
__device__ float g_Wg[DMODEL * 384];        // g ⊙ folded W
__device__ float g_M2[DM * 384];            // WA @ Wg
__device__ float g_S[384];                  // colsum(Wg)
__device__ float g_C[384];                  // beta@Wfold + folded bias
__device__ float g_PQ2[(size_t)12416 * 384]; // rows: [0,6272)=P@Wg per (b,i); [6272,12416)=Q@Wg per (b,j)

// ---------------- helpers ----------------
__device__ __forceinline__ float warp_sum(float v) {
    #pragma unroll
    for (int o = 16; o > 0; o >>= 1) v += __shfl_xor_sync(0xffffffffu, v, o);
    return v;
}
__device__ __forceinline__ float warp_max(float v) {
    #pragma unroll
    for (int o = 16; o > 0; o >>= 1) v = fmaxf(v, __shfl_xor_sync(0xffffffffu, v, o));
    return v;
}
__device__ __forceinline__ unsigned rotl32(unsigned v, int r) { return (v << r) | (v >> (32 - r)); }
__device__ __forceinline__ ull fma2(ull a, ull b, ull c) {
    ull d; asm("fma.rn.f32x2 %0, %1, %2, %3;" : "=l"(d) : "l"(a), "l"(b), "l"(c)); return d;
}
__device__ __forceinline__ ull add2(ull a, ull b) {
    ull d; asm("add.rn.f32x2 %0, %1, %2;" : "=l"(d) : "l"(a), "l"(b)); return d;
}
__device__ __forceinline__ ull pack2(float lo, float hi) {
    ull d; asm("mov.b64 %0, {%1, %2};" : "=l"(d) : "f"(lo), "f"(hi)); return d;
}
__device__ __forceinline__ ull dup2(float v) {
    ull d; asm("mov.b64 %0, {%1, %1};" : "=l"(d) : "f"(v)); return d;
}
__device__ __forceinline__ void unpack2(ull v, float& lo, float& hi) {
    asm("mov.b64 {%0, %1}, %2;" : "=f"(lo), "=f"(hi) : "l"(v));
}
__device__ float gumbel_noise(unsigned idx) {   // JAX partitionable threefry (verified R2-R6)
    unsigned x0 = 0u, x1 = idx;
    const unsigned ks0 = 0u, ks1 = 42u, ks2 = 0x1BD11BDAu ^ 0u ^ 42u;
    x0 += ks0; x1 += ks1;
#define TFR(r) { x0 += x1; x1 = rotl32(x1, r); x1 ^= x0; }
    TFR(13) TFR(15) TFR(26) TFR(6)   x0 += ks1; x1 += ks2 + 1u;
    TFR(17) TFR(29) TFR(16) TFR(24)  x0 += ks2; x1 += ks0 + 2u;
    TFR(13) TFR(15) TFR(26) TFR(6)   x0 += ks0; x1 += ks1 + 3u;
    TFR(17) TFR(29) TFR(16) TFR(24)  x0 += ks1; x1 += ks2 + 4u;
    TFR(13) TFR(15) TFR(26) TFR(6)   x0 += ks2; x1 += ks0 + 5u;
#undef TFR
    unsigned bits = x0 ^ x1;
    float u = __uint_as_float((bits >> 9) | 0x3f800000u) - 1.0f;
    return -logf(-log1pf(-u));
}

// ---------------- k0: build Wg, S, C, M2 ----------------
// block per output col n (384 blocks, 128 threads: thread = d)
__global__ void k0_fold(const float* __restrict__ W_qkv, const float* __restrict__ b_qkv,
                        const float* __restrict__ W1, const float* __restrict__ b1,
                        const float* __restrict__ ln_g, const float* __restrict__ ln_b,
                        const float* __restrict__ W_embed) {
    int n = blockIdx.x, d = threadIdx.x;
    const float scale = 0.1767766952966369f;  // 32^-0.5
    int h = (n - 256) >> 5, dp = (n - 256) & 31;
    float wf;
    if (n < 128) wf = W_qkv[d * 384 + n] * scale;
    else if (n < 256) wf = W_qkv[d * 384 + n];
    else {
        float acc = 0.f;
        #pragma unroll 8
        for (int c = 0; c < 32; c++)
            acc = fmaf(W_qkv[d * 384 + 256 + 32 * h + c], W1[c * 32 + dp], acc);
        wf = acc;
    }
    float wg = ln_g[d] * wf;
    g_Wg[d * 384 + n] = wg;
    __shared__ float sw[128], red[128];
    sw[d] = wg;
    red[d] = wg;
    __syncthreads();
    for (int s = 64; s > 0; s >>= 1) { if (d < s) red[d] += red[d + s]; __syncthreads(); }
    float Sv = red[0];
    __syncthreads();
    red[d] = ln_b[d] * wf;
    __syncthreads();
    for (int s = 64; s > 0; s >>= 1) { if (d < s) red[d] += red[d + s]; __syncthreads(); }
    if (d == 0) {
        float bias;
        if (n < 128) bias = b_qkv[n] * scale;
        else if (n < 256) bias = b_qkv[n];
        else {
            bias = b1[dp];
            #pragma unroll 8
            for (int c = 0; c < 32; c++)
                bias = fmaf(b_qkv[256 + 32 * h + c], W1[c * 32 + dp], bias);
        }
        g_S[n] = Sv;
        g_C[n] = red[0] + bias;
    }
    if (d < 32) {
        float acc = 0.f;
        #pragma unroll 16
        for (int dd = 0; dd < 128; dd++)
            acc = fmaf(W_embed[(64 + d) * 128 + dd], sw[dd], acc);
        g_M2[d * 384 + n] = acc;
    }
}

// ---------------- k1: P, Q ----------------
__global__ void k1_pq(const float* __restrict__ x, const float* __restrict__ attn_mask,
                      const float* __restrict__ W_embed, const float* __restrict__ b_embed) {
    int b = blockIdx.x / NP1, n = blockIdx.x % NP1, d = threadIdx.x;
    if (n == NN) { g_P[((size_t)b * NP1 + NN) * DMODEL + d] = b_embed[d]; return; }
    __shared__ float am[NN];
    __shared__ float xm[DM];
    if (d < NN) am[d] = attn_mask[((size_t)b * NN + n) * NN + d];
    __syncthreads();
    float s = 0.f;
    #pragma unroll
    for (int c = 0; c < NN; c++) s += am[c];
    if (d < DM) xm[d] = x[((size_t)b * NN + n) * DM + d] * ((s > 0.f) ? 1.f : 0.f);
    __syncthreads();
    float p = b_embed[d], q = 0.f;
    #pragma unroll
    for (int c = 0; c < DM; c++) {
        float xc = xm[c];
        p = fmaf(xc, W_embed[c * DMODEL + d], p);
        q = fmaf(xc, W_embed[(DM + c) * DMODEL + d], q);
    }
    g_P[((size_t)b * NP1 + n) * DMODEL + d] = p;
    g_Q[((size_t)b * NN + n) * DMODEL + d] = q;
}

// ---------------- kP: P2/Q2 = [P;Q] @ Wg (12416 x 384, K=128) ----------------
__global__ void __launch_bounds__(256) kP_gemm() {
    __shared__ float wt[16 * 384];
    int tid = threadIdx.x, lane = tid & 31, w = tid >> 5;
    int base = blockIdx.x * 56;
    ull acc2[7][6];
    #pragma unroll
    for (int rr = 0; rr < 7; rr++)
        #pragma unroll
        for (int k = 0; k < 6; k++) acc2[rr][k] = 0ull;
    for (int d0 = 0; d0 < DMODEL; d0 += 16) {
        for (int t = tid; t < 16 * 384 / 4; t += 256)
            ((float4*)wt)[t] = ((const float4*)(g_Wg + (size_t)d0 * 384))[t];
        __syncthreads();
        float eReg[7];
        #pragma unroll
        for (int rr = 0; rr < 7; rr++) {
            int gr = base + w + 8 * rr;
            float v = 0.f;
            if (gr < 12416 && (lane < 16)) {
                v = (gr < 6272) ? g_P[(size_t)gr * DMODEL + d0 + lane]
                                : g_Q[(size_t)(gr - 6272) * DMODEL + d0 + lane];
            }
            eReg[rr] = v;
        }
        #pragma unroll 4
        for (int dd = 0; dd < 16; dd++) {
            ulonglong2 wv0 = ((const ulonglong2*)(wt + dd * 384))[lane];
            ulonglong2 wv1 = ((const ulonglong2*)(wt + dd * 384 + 128))[lane];
            ulonglong2 wv2 = ((const ulonglong2*)(wt + dd * 384 + 256))[lane];
            #pragma unroll
            for (int rr = 0; rr < 7; rr++) {
                ull e2 = dup2(__shfl_sync(0xffffffffu, eReg[rr], dd));
                acc2[rr][0] = fma2(e2, wv0.x, acc2[rr][0]);
                acc2[rr][1] = fma2(e2, wv0.y, acc2[rr][1]);
                acc2[rr][2] = fma2(e2, wv1.x, acc2[rr][2]);
                acc2[rr][3] = fma2(e2, wv1.y, acc2[rr][3]);
                acc2[rr][4] = fma2(e2, wv2.x, acc2[rr][4]);
                acc2[rr][5] = fma2(e2, wv2.y, acc2[rr][5]);
            }
        }
        __syncthreads();
    }
    #pragma unroll
    for (int rr = 0; rr < 7; rr++) {
        int gr = base + w + 8 * rr;
        if (gr < 12416) {
            #pragma unroll
            for (int k4 = 0; k4 < 3; k4++) {
                float v0, v1, v2, v3;
                unpack2(acc2[rr][2*k4], v0, v1);
                unpack2(acc2[rr][2*k4+1], v2, v3);
                *(float4*)(g_PQ2 + (size_t)gr * 384 + 128 * k4 + 4 * lane) = make_float4(v0, v1, v2, v3);
            }
        }
    }
}

// ---------------- k3 smem layout (floats) ----------------
#define OFF_AE  0        /* 56*32 = 1792, persists */
#define OFF_BIG 1920
  /* phase A: sWA @1920 (4096)        */
  /* phase B: sM2 @1920 (12288) ->14208 */
#define QSTR    132
#define OFF_Q   1920     /* 49*132=6468 ->8388 */
#define OFF_V   8388     /* ->14856 */
#define KTSTR   52
#define OFF_KT  14856    /* 128*52=6656 ->21512 */
#define OFF_M   21512    /* 64 */
#define OFF_S   21576    /* 384 */
#define OFF_C   21960    /* 384 */
#define OFF_W2  22344    /* 32 */
#define OFF_G   22376    /* 200 -> 22576 */
#define SMEM3_FLOATS 22576
#define SMEM3_BYTES (SMEM3_FLOATS * 4)

__global__ void __launch_bounds__(256, 2) k3_attn(
    const float* __restrict__ A, const float* __restrict__ attn_mask,
    const float* __restrict__ W_embed, const float* __restrict__ W2,
    const float* __restrict__ b2, float* __restrict__ out) {
    extern __shared__ float sm[];
    int bj = blockIdx.x, b = bj / NN, j = bj % NN;
    int tid = threadIdx.x, lane = tid & 31, w = tid >> 5;
    bool wzero = (w == 0);
    float* sAE = sm + OFF_AE;
    float* sWA = sm + OFF_BIG;
    float* sM2 = sm + OFF_BIG;
    float* sQ  = sm + OFF_Q;
    float* sV  = sm + OFF_V;
    float* sKT = sm + OFF_KT;
    float* sM  = sm + OFF_M;
    float* sS  = sm + OFF_S;
    float* sC  = sm + OFF_C;
    float* sW2 = sm + OFF_W2;
    float* sG  = sm + OFF_G;

    // ---- init loads ----
    if (tid < 64) sM[tid] = (tid < NN) ? attn_mask[((size_t)b * NN + j) * NN + tid]
                                       : (tid == NN ? 1.0f : 0.0f);
    for (int t = tid; t < 384; t += 256) { sS[t] = g_S[t]; sC[t] = g_C[t]; }
    if (tid < 32) sW2[tid] = W2[tid];
    for (int t = tid; t < DM * DMODEL; t += 256) sWA[t] = W_embed[(2 * DM) * DMODEL + t];
    for (int t = tid; t < 128 * 3; t += 256) sKT[(t / 3) * KTSTR + 49 + (t % 3)] = 0.f;
    __syncthreads();

    // ---- stage masked A rows ----
    #pragma unroll
    for (int rr = 0; rr < 7; rr++) {
        int row = w + 8 * rr;
        if (rr < 6 || wzero) {
            float a = 0.f;
            if (row < NN) a = A[(((size_t)b * NN + row) * NN + j) * DM + lane] * sM[row];
            sAE[(w * 7 + rr) * DM + lane] = a;
        }
    }
    __syncwarp();

    // ---- LN stats: raw = P + Q + a@WA; mu, rs kept in regs ----
    float rsR[7], msR[7];
    {
        const float2* Pb2 = (const float2*)(g_P + (size_t)b * NP1 * DMODEL);
        const float2* Qb2 = (const float2*)(g_Q + ((size_t)b * NN + j) * DMODEL);
        const ull* wt2 = (const ull*)sWA;
        float2 qva = Qb2[lane], qvb = Qb2[32 + lane];
        ull e0[7], e1[7];
        #pragma unroll
        for (int rr = 0; rr < 7; rr++) {
            int row = w + 8 * rr;
            if (rr < 6 || wzero) {
                float2 p0 = Pb2[row * 64 + lane], p1 = Pb2[row * 64 + 32 + lane];
                e0[rr] = pack2(p0.x + qva.x, p0.y + qva.y);
                e1[rr] = pack2(p1.x + qvb.x, p1.y + qvb.y);
            }
        }
        #pragma unroll 2
        for (int cg = 0; cg < 8; cg++) {
            float4 a4[7];
            #pragma unroll
            for (int rr = 0; rr < 7; rr++)
                if (rr < 6 || wzero) a4[rr] = *(const float4*)(sAE + (w * 7 + rr) * DM + 4 * cg);
            #pragma unroll
            for (int t = 0; t < 4; t++) {
                int c = 4 * cg + t;
                ull wv0 = wt2[c * 64 + lane], wv1 = wt2[c * 64 + 32 + lane];
                #pragma unroll
                for (int rr = 0; rr < 7; rr++) {
                    if (rr < 6 || wzero) {
                        ull ac = dup2(((const float*)&a4[rr])[t]);
                        e0[rr] = fma2(ac, wv0, e0[rr]);
                        e1[rr] = fma2(ac, wv1, e1[rr]);
                    }
                }
            }
        }
        #pragma unroll
        for (int rr = 0; rr < 7; rr++) {
            if (rr < 6 || wzero) {
                float v0, v1, v2, v3;
                unpack2(e0[rr], v0, v1); unpack2(e1[rr], v2, v3);
                float mu = warp_sum(v0 + v1 + v2 + v3) * (1.0f / DMODEL);
                float d0 = v0 - mu, d1 = v1 - mu, d2 = v2 - mu, d3 = v3 - mu;
                float rs = rsqrtf(warp_sum(d0*d0 + d1*d1 + d2*d2 + d3*d3) * (1.0f / DMODEL) + 1e-5f);
                rsR[rr] = rs;
                msR[rr] = rs * mu;
            }
        }
    }
    __syncthreads();

    // ---- load M2 tile (overwrites sWA region) ----
    for (int t = tid; t < DM * 384 / 4; t += 256)
        ((float4*)sM2)[t] = ((const float4*)g_M2)[t];
    __syncthreads();

    // ---- qkv: acc = P2 + Q2 + a@M2 ; out = rs*acc - (rs*mu)*S + C ----
    ull acc2[7][6];
    {
        const ull* q2p = (const ull*)(g_PQ2 + (size_t)(6272 + b * NN + j) * 384);
        ull q2u[6];
        #pragma unroll
        for (int k4 = 0; k4 < 3; k4++) {
            q2u[2*k4]   = q2p[64 * k4 + 2 * lane];
            q2u[2*k4+1] = q2p[64 * k4 + 2 * lane + 1];
        }
        #pragma unroll
        for (int rr = 0; rr < 7; rr++) {
            int row = w + 8 * rr;
            if (rr < 6 || wzero) {
                const float4* p2r = (const float4*)(g_PQ2 + (size_t)(b * NP1 + row) * 384);
                #pragma unroll
                for (int k4 = 0; k4 < 3; k4++) {
                    float4 p4 = p2r[32 * k4 + lane];
                    acc2[rr][2*k4]   = add2(pack2(p4.x, p4.y), q2u[2*k4]);
                    acc2[rr][2*k4+1] = add2(pack2(p4.z, p4.w), q2u[2*k4+1]);
                }
            }
        }
        #pragma unroll 2
        for (int cg = 0; cg < 8; cg++) {
            float4 a4[7];
            #pragma unroll
            for (int rr = 0; rr < 7; rr++)
                if (rr < 6 || wzero) a4[rr] = *(const float4*)(sAE + (w * 7 + rr) * DM + 4 * cg);
            #pragma unroll
            for (int t = 0; t < 4; t++) {
                int c = 4 * cg + t;
                ulonglong2 wv0 = ((const ulonglong2*)(sM2 + c * 384))[lane];
                ulonglong2 wv1 = ((const ulonglong2*)(sM2 + c * 384 + 128))[lane];
                ulonglong2 wv2 = ((const ulonglong2*)(sM2 + c * 384 + 256))[lane];
                #pragma unroll
                for (int rr = 0; rr < 7; rr++) {
                    if (rr < 6 || wzero) {
                        ull ac = dup2(((const float*)&a4[rr])[t]);
                        acc2[rr][0] = fma2(ac, wv0.x, acc2[rr][0]);
                        acc2[rr][1] = fma2(ac, wv0.y, acc2[rr][1]);
                        acc2[rr][2] = fma2(ac, wv1.x, acc2[rr][2]);
                        acc2[rr][3] = fma2(ac, wv1.y, acc2[rr][3]);
                        acc2[rr][4] = fma2(ac, wv2.x, acc2[rr][4]);
                        acc2[rr][5] = fma2(ac, wv2.y, acc2[rr][5]);
                    }
                }
            }
        }
    }
    __syncthreads();   // all warps done reading sM2 before scatter overwrites it

    // ---- epilogue + scatter q / k^T / v' ----
    const ull* sS2 = (const ull*)sS;
    const ull* sC2 = (const ull*)sC;
    #pragma unroll
    for (int rr = 0; rr < 7; rr++) {
        int row = w + 8 * rr;
        if (rr < 6 || wzero) {
            ull rs2 = dup2(rsR[rr]), nm2 = dup2(-msR[rr]);
            float o[12];
            #pragma unroll
            for (int k4 = 0; k4 < 3; k4++) {
                #pragma unroll
                for (int u = 0; u < 2; u++) {
                    int k = 2 * k4 + u;
                    ull sv = sS2[64 * k4 + 2 * lane + u];
                    ull cv = sC2[64 * k4 + 2 * lane + u];
                    ull res = fma2(rs2, acc2[rr][k], fma2(nm2, sv, cv));
                    unpack2(res, o[4*k4 + 2*u], o[4*k4 + 2*u + 1]);
                }
            }
            *(float4*)(sQ + row * QSTR + 4 * lane) = make_float4(o[0], o[1], o[2], o[3]);
            *(float4*)(sV + row * QSTR + 4 * lane) = make_float4(o[8], o[9], o[10], o[11]);
            int kd = 4 * lane;
            sKT[kd * KTSTR + row] = o[4];
            sKT[(kd + 1) * KTSTR + row] = o[5];
            sKT[(kd + 2) * KTSTR + row] = o[6];
            sKT[(kd + 3) * KTSTR + row] = o[7];
        }
    }
    __syncthreads();

    // ---- attention: blk = (head h, 7 i-rows) ----
    float b2v = b2[0], w2r = sW2[lane];
    float m0 = sM[2 * lane], m1 = sM[2 * lane + 1];
    bool vj0 = (2 * lane) < NP1, vj1 = (2 * lane + 1) < NP1;
    for (int blk = w; blk < 28; blk += 8) {
        int h = blk & 3, ibase = (blk >> 2) * 7;
        ull s2[7];
        #pragma unroll
        for (int r = 0; r < 7; r++) s2[r] = 0ull;
        const float* ktb = sKT + (h * HD) * KTSTR + 2 * lane;
        #pragma unroll 2
        for (int dq = 0; dq < 8; dq++) {
            float4 q4[7];
            #pragma unroll
            for (int r = 0; r < 7; r++)
                q4[r] = *(const float4*)(sQ + (ibase + r) * QSTR + h * HD + 4 * dq);
            #pragma unroll
            for (int t = 0; t < 4; t++) {
                int d = 4 * dq + t;
                ull kv2 = (lane < 26) ? *(const ull*)(ktb + d * KTSTR) : 0ull;
                #pragma unroll
                for (int r = 0; r < 7; r++) {
                    ull qd = dup2(((const float*)&q4[r])[t]);
                    s2[r] = fma2(qd, kv2, s2[r]);
                }
            }
        }
        ull p2[7];
        float invr[7];
        #pragma unroll
        for (int r = 0; r < 7; r++) {
            float mi = sM[ibase + r];
            float s0, s1;
            unpack2(s2[r], s0, s1);
            s0 = vj0 ? ((mi * m0 > 0.f) ? s0 : -1e9f) : -INFINITY;
            s1 = vj1 ? ((mi * m1 > 0.f) ? s1 : -1e9f) : -INFINITY;
            float mx = warp_max(fmaxf(s0, s1));
            float e0 = vj0 ? expf(s0 - mx) : 0.f;
            float e1 = vj1 ? expf(s1 - mx) : 0.f;
            invr[r] = 1.0f / warp_sum(e0 + e1);
            p2[r] = pack2(e0, e1);
        }
        ull t2[7];
        #pragma unroll
        for (int r = 0; r < 7; r++) t2[r] = 0ull;
        const float* vb = sV + h * HD + lane;
        #pragma unroll 5
        for (int jp = 0; jp < 25; jp++) {
            ull v2 = pack2(vb[(2 * jp) * QSTR], vb[(2 * jp + 1) * QSTR]);
            #pragma unroll
            for (int r = 0; r < 7; r++) {
                ull pp = __shfl_sync(0xffffffffu, p2[r], jp);
                t2[r] = fma2(pp, v2, t2[r]);
            }
        }
        #pragma unroll
        for (int r = 0; r < 7; r++) {
            float tlo, thi;
            unpack2(t2[r], tlo, thi);
            float t = fmaxf((tlo + thi) * invr[r], 0.f);
            float gp = warp_sum(t * w2r);
            if (lane == 0) sG[h * NP1 + ibase + r] = gp + b2v;
        }
    }
    __syncthreads();

    // ---- em softmax + gumbel (warp = head) ----
    if (w < NHEAD) {
        int h = w, i0 = lane, i1 = lane + 32;
        bool has1 = (i1 < NP1);
        float g0 = sG[h * NP1 + i0];
        float g1 = has1 ? sG[h * NP1 + i1] : -INFINITY;
        float mx = warp_max(fmaxf(g0, g1));
        float e0 = expf(g0 - mx), e1 = has1 ? expf(g1 - mx) : 0.f;
        float inv = 1.0f / warp_sum(e0 + e1);
        float em0 = e0 * inv * sM[i0];
        float em1 = has1 ? e1 * inv * sM[i1] : 0.f;
        float den = warp_sum(em0 + em1) + 1e-10f;
        em0 /= den; em1 /= den;
        size_t base = (((size_t)b * NN + j) * NHEAD + h) * NP1;
        out[base + i0] = em0;
        if (has1) out[base + i1] = em1;
        float l0 = logf(em0 + 1e-10f) + gumbel_noise((unsigned)(base + i0));
        float l1 = has1 ? (logf(em1 + 1e-10f) + gumbel_noise((unsigned)(base + i1))) : -INFINITY;
        float mx2 = warp_max(fmaxf(l0, l1));
        float t0 = expf(l0 - mx2), t1 = has1 ? expf(l1 - mx2) : 0.f;
        float inv2 = 1.0f / warp_sum(t0 + t1);
        out[TOTALE + base + i0] = t0 * inv2;
        if (has1) out[TOTALE + base + i1] = t1 * inv2;
    }
}

// ---------------- launch ----------------
extern "C" void kernel_launch(void* const* d_in, const int* in_sizes, int n_in,
                              void* d_out, int out_size) {
    const float* x       = (const float*)d_in[0];
    const float* A       = (const float*)d_in[1];
    const float* amask   = (const float*)d_in[2];
    const float* W_embed = (const float*)d_in[3];
    const float* b_embed = (const float*)d_in[4];
    const float* ln_g    = (const float*)d_in[5];
    const float* ln_b    = (const float*)d_in[6];
    const float* W_qkv   = (const float*)d_in[7];
    const float* b_qkv   = (const float*)d_in[8];
    const float* W1      = (const float*)d_in[9];
    const float* b1      = (const float*)d_in[10];
    const float* W2      = (const float*)d_in[11];
    const float* b2      = (const float*)d_in[12];
    float* out = (float*)d_out;

    cudaFuncSetAttribute(k3_attn, cudaFuncAttributeMaxDynamicSharedMemorySize, SMEM3_BYTES);

    k0_fold<<<384, 128>>>(W_qkv, b_qkv, W1, b1, ln_g, ln_b, W_embed);
    k1_pq<<<BSZ * NP1, 128>>>(x, amask, W_embed, b_embed);
    kP_gemm<<<(12416 + 55) / 56, 256>>>();
    k3_attn<<<BSZ * NN, 256, SMEM3_BYTES>>>(A, amask, W_embed, W2, b2, out);
}